// round 10
// baseline (speedup 1.0000x reference)
#include <cuda_runtime.h>
#include <cstdint>

#define BB    4
#define CC    256
#define HH    256
#define WW2   256
#define HW    65536          // HH*WW2
#define NPIX  262144         // BB*HW
#define NTILE 2048           // NPIX/128
#define HEADS 8
#define HD    32
#define NWIN  1024           // (HH/8)*(WW2/8)

// Scratch: q, k, v, attention-output, each [B][C][H][W] fp32 (256 MB each).
__device__ float g_q [BB * CC * HW];
__device__ float g_k [BB * CC * HW];
__device__ float g_v [BB * CC * HW];
__device__ float g_ao[BB * CC * HW];

// Pre-swizzled weights in mma-fragment order (tf32 bits).
// Layout: [mat(4)][mtile(16)][ktile(32)][lane(32)][slot(4)]
__device__ uint32_t g_swzW[4 * 16 * 32 * 128];

__device__ __forceinline__ uint32_t f2tf32(float f) {
    uint32_t u;
    asm("cvt.rna.tf32.f32 %0, %1;" : "=r"(u) : "f"(f));
    return u;
}

__device__ __forceinline__ void mma_tf32(float& c0, float& c1, float& c2, float& c3,
                                         uint32_t a0, uint32_t a1, uint32_t a2, uint32_t a3,
                                         uint32_t b0, uint32_t b1) {
    asm volatile(
        "mma.sync.aligned.m16n8k8.row.col.f32.tf32.tf32.f32 "
        "{%0,%1,%2,%3}, {%4,%5,%6,%7}, {%8,%9}, {%0,%1,%2,%3};\n"
        : "+f"(c0), "+f"(c1), "+f"(c2), "+f"(c3)
        : "r"(a0), "r"(a1), "r"(a2), "r"(a3), "r"(b0), "r"(b1));
}

// ---------------------------------------------------------------------------
// One-shot weight pre-swizzle: W[m][k] (row-major 256x256) -> fragment order.
// ---------------------------------------------------------------------------
__global__ __launch_bounds__(256) void swz_kernel(const float* __restrict__ Wq,
                                                  const float* __restrict__ Wk,
                                                  const float* __restrict__ Wv,
                                                  const float* __restrict__ Wo)
{
    int idx = blockIdx.x * 256 + threadIdx.x;      // 65536 total
    int lane = idx & 31;
    int kt   = (idx >> 5) & 31;
    int mt   = (idx >> 10) & 15;
    int mat  = idx >> 14;
    const float* W = (mat == 0) ? Wq : (mat == 1) ? Wk : (mat == 2) ? Wv : Wo;

    uint32_t o[4];
#pragma unroll
    for (int s = 0; s < 4; s++) {
        int r = (lane >> 2) + (s & 1) * 8;
        int c = (lane & 3) + (s >> 1) * 4;
        o[s] = f2tf32(W[(mt * 16 + r) * CC + kt * 8 + c]);
    }
    uint4* dst = reinterpret_cast<uint4*>(&g_swzW[(size_t)idx * 4]);
    *dst = make_uint4(o[0], o[1], o[2], o[3]);
}

// ---------------------------------------------------------------------------
// Multi-pass tf32 GEMM with RESIDENT B: one block stages the full 128(p) x
// 256(k) B tile (fragment order, tf32) into smem ONCE, then runs npass GEMM
// passes over it (qkv: 6 = 3 mats x 2 m-halves; wo: 2), re-staging only A.
// Dynamic smem: Bs = 16 chunks x 2112 u32, As = 2 x 2112 u32 (148.5 KB).
// ---------------------------------------------------------------------------
#define BS_CHUNK   2112
#define BS_TOTAL   (16 * BS_CHUNK)
#define SMEM_GEMM_BYTES ((BS_TOTAL + 2 * BS_CHUNK) * 4)

__global__ __launch_bounds__(256, 1) void gemm_multi_kernel(const float* __restrict__ x,
                                                            int mode,          // 0=qkv, 1=wo
                                                            float* __restrict__ wo_out)
{
    extern __shared__ uint32_t sh[];
    uint32_t* Bs = sh;                       // [16][2112]
    uint32_t* As = sh + BS_TOTAL;            // [2][2112]

    const int tid  = threadIdx.x;
    const int w8   = tid >> 5;
    const int lane = tid & 31;
    const int wm   = w8 & 1;
    const int wn   = w8 >> 1;

    const float* X = (mode == 0) ? x : g_ao;

    const int p0  = blockIdx.x * 128;
    const int b   = p0 >> 16;
    const int hw0 = p0 & (HW - 1);
    const float* Xb = X + (size_t)b * CC * HW + hw0;

    // ---- Phase 1: stage ALL of B (256 k x 128 p), fragment order, tf32 ----
    {
        // thread covers (wj, l) slots: k = 2*(wj&7)+h within chunk, 64-col half wj>>3
        const int wj = tid >> 5;
        const int l  = tid & 31;
        const int h  = l >> 4;
        const int m  = l & 15;
        const int kk = 2 * (wj & 7) + h;           // same for both u via +8 warp offset trick
        (void)kk;
#pragma unroll 4
        for (int kc = 0; kc < 16; kc++) {
#pragma unroll
            for (int u = 0; u < 2; u++) {
                int j   = tid + u * 256;
                int wjj = j >> 5;
                int ll  = j & 31;
                int hh  = ll >> 4;
                int mm  = ll & 15;
                int k   = 2 * (wjj & 7) + hh;
                int pf  = ((wjj >> 3) * 16 + mm) * 4;
                float4 bv = *reinterpret_cast<const float4*>(
                    Xb + (size_t)(kc * 16 + k) * HW + pf);
                int ktl = k >> 3, ch = k & 7;
                int slot = ch >> 2, cl = ch & 3;
                int sl2 = slot ^ (cl & 1);
                float vals[4] = {bv.x, bv.y, bv.z, bv.w};
#pragma unroll
                for (int e = 0; e < 4; e++) {
                    int p  = pf + e;
                    int nt = p >> 3;
                    int n  = p & 7;
                    int off = (n * 4 + cl) * 2 + sl2;
                    off ^= (n & 4) << 2;           // intra-tile swizzle only
                    Bs[kc * BS_CHUNK + (ktl * 16 + nt) * 66 + off] = f2tf32(vals[e]);
                }
            }
        }
    }
    __syncthreads();

    const int blx = (lane * 2) ^ (lane & 16);
    const bool bswap = (lane & 1);
    const int npass = (mode == 0) ? 6 : 2;

    uint4 aR[2];

    for (int ps = 0; ps < npass; ps++) {
        const int mat   = (mode == 0) ? (ps >> 1) : 3;
        const int mhalf = ps & 1;
        const uint32_t* Wz = g_swzW + ((size_t)mat * 16 + mhalf * 8) * 32 * 128;
        float* Out = (mode == 0) ? ((mat == 0) ? g_q : (mat == 1) ? g_k : g_v) : wo_out;
        float* Ob  = Out + (size_t)b * CC * HW + hw0;
        const int mBase = mhalf * 128;

        float acc[4][4][4];
#pragma unroll
        for (int i = 0; i < 4; i++)
#pragma unroll
            for (int j = 0; j < 4; j++)
#pragma unroll
                for (int e = 0; e < 4; e++) acc[i][j][e] = 0.f;

        auto ldgA = [&](int kc) {
#pragma unroll
            for (int u = 0; u < 2; u++) {
                int j = tid + u * 256;
                int t = j >> 5;
                int l = j & 31;
                int ktl = t >> 3, mt = t & 7;
                aR[u] = *reinterpret_cast<const uint4*>(
                    Wz + ((size_t)mt * 32 + (size_t)(kc * 2 + ktl)) * 128 + l * 4);
            }
        };
        auto stsA = [&](int buf) {
#pragma unroll
            for (int u = 0; u < 2; u++) {
                int j = tid + u * 256;
                int t = j >> 5;
                int l = j & 31;
                *reinterpret_cast<uint4*>(&As[buf * BS_CHUNK + t * 132 + l * 4]) = aR[u];
            }
        };
        auto domma = [&](int buf, int kc) {
            const uint32_t* Bc = Bs + kc * BS_CHUNK;
#pragma unroll
            for (int kt = 0; kt < 2; kt++) {
                uint4 a[4];
                uint32_t b0[4], b1[4];
#pragma unroll
                for (int mt = 0; mt < 4; mt++)
                    a[mt] = *reinterpret_cast<const uint4*>(
                        &As[buf * BS_CHUNK + (kt * 8 + wm * 4 + mt) * 132 + lane * 4]);
#pragma unroll
                for (int nt = 0; nt < 4; nt++) {
                    uint2 raw = *reinterpret_cast<const uint2*>(
                        &Bc[(kt * 16 + wn * 4 + nt) * 66 + blx]);
                    b0[nt] = bswap ? raw.y : raw.x;
                    b1[nt] = bswap ? raw.x : raw.y;
                }
#pragma unroll
                for (int mt = 0; mt < 4; mt++)
#pragma unroll
                    for (int nt = 0; nt < 4; nt++)
                        mma_tf32(acc[mt][nt][0], acc[mt][nt][1], acc[mt][nt][2], acc[mt][nt][3],
                                 a[mt].x, a[mt].y, a[mt].z, a[mt].w, b0[nt], b1[nt]);
            }
        };

        ldgA(0);
        stsA(0);
        __syncthreads();
#pragma unroll 1
        for (int kc = 0; kc < 16; kc++) {
            if (kc < 15) ldgA(kc + 1);
            domma(kc & 1, kc);
            if (kc < 15) {
                stsA((kc + 1) & 1);
                __syncthreads();
            }
        }

        // epilogue
#pragma unroll
        for (int mt = 0; mt < 4; mt++) {
#pragma unroll
            for (int nt = 0; nt < 4; nt++) {
                int m   = mBase + wm * 64 + mt * 16 + (lane >> 2);
                int col = wn * 32 + nt * 8 + (lane & 3) * 2;
                float* r0 = Ob + (size_t)m * HW + col;
                *reinterpret_cast<float2*>(r0) = make_float2(acc[mt][nt][0], acc[mt][nt][1]);
                *reinterpret_cast<float2*>(r0 + (size_t)8 * HW) =
                    make_float2(acc[mt][nt][2], acc[mt][nt][3]);
            }
        }
        __syncthreads();   // protect As before next pass restages
    }
}

// ---------------------------------------------------------------------------
// Tensor-core windowed attention. Block = 64 threads = 2 warps = one
// (window, head). Warp w owns S/O rows [32w, 32w+32).
// Smem (27 KB -> 8 CTAs/SM): Vt[2304]; KQ[4608] holds Kt (0..2304) and
// Qw[w] (2304 + w*1152) during the S phase, then is REUSED for Pw[w]
// (w*2176) after a __syncthreads() — P is only written once all Kt/Qw
// reads are complete.
// ---------------------------------------------------------------------------
__global__ __launch_bounds__(64) void attn_tc_kernel()
{
    __shared__ uint32_t Vt[32 * 72];     // 2304
    __shared__ uint32_t KQ[4608];        // Kt | Qw  -> later Pw

    const int bidx = blockIdx.x;
    const int head = bidx & 7;
    const int win  = bidx >> 3;
    const int b    = win >> 10;
    const int wh   = (win >> 5) & 31;
    const int ww   = win & 31;
    const int tid  = threadIdx.x;
    const int w    = tid >> 5;
    const int lane = tid & 31;

    uint32_t* Kt = KQ;
    uint32_t* Qw = KQ + 2304 + w * 1152;   // stride 36 rows
    uint32_t* Pw = KQ + w * 2176;          // stride 68 rows (valid after sync)

    const size_t base = (size_t)b * CC * HW + (size_t)(head * HD) * HW
                      + (size_t)(wh * 8) * WW2 + (size_t)(ww * 8);

    // ---- load: thread = token j ----
    {
        const int j = tid;
        const size_t off = base + (size_t)(j >> 3) * WW2 + (j & 7);
        const float scale = 0.17677669529663687f;   // 32^-0.5
        const int qsw = ((lane >> 3) & 3) << 3;
#pragma unroll
        for (int c = 0; c < HD; c++) {
            size_t a = off + (size_t)c * HW;
            Kt[c * 72 + j] = f2tf32(g_k[a]);
            Vt[c * 72 + j] = f2tf32(g_v[a]);
            Qw[lane * 36 + (c ^ qsw)] = f2tf32(g_q[a] * scale);
        }
    }
    __syncthreads();

    // ---- S = Q^T K ----
    float s[2][8][4];
#pragma unroll
    for (int mt = 0; mt < 2; mt++)
#pragma unroll
        for (int nt = 0; nt < 8; nt++)
#pragma unroll
            for (int e = 0; e < 4; e++) s[mt][nt][e] = 0.f;

#pragma unroll
    for (int kt = 0; kt < 4; kt++) {
        uint32_t a[2][4];
#pragma unroll
        for (int mt = 0; mt < 2; mt++)
#pragma unroll
            for (int sl = 0; sl < 4; sl++) {
                int ir = (lane >> 2) + 8 * (sl & 1) + 16 * mt;
                int c  = (lane & 3) + 4 * (sl >> 1) + 8 * kt;
                int ks = ((ir >> 3) & 3) << 3;
                a[mt][sl] = Qw[ir * 36 + (c ^ ks)];
            }
#pragma unroll
        for (int nt = 0; nt < 8; nt++) {
            int cb = 8 * kt + (lane & 3);
            int jj = 8 * nt + (lane >> 2);
            uint32_t b0 = Kt[cb * 72 + jj];
            uint32_t b1 = Kt[(cb + 4) * 72 + jj];
#pragma unroll
            for (int mt = 0; mt < 2; mt++)
                mma_tf32(s[mt][nt][0], s[mt][nt][1], s[mt][nt][2], s[mt][nt][3],
                         a[mt][0], a[mt][1], a[mt][2], a[mt][3], b0, b1);
        }
    }

    // ---- softmax (register-only) ----
    float mx[2][2] = {{-1e30f, -1e30f}, {-1e30f, -1e30f}};
#pragma unroll
    for (int mt = 0; mt < 2; mt++)
#pragma unroll
        for (int nt = 0; nt < 8; nt++) {
            mx[mt][0] = fmaxf(mx[mt][0], fmaxf(s[mt][nt][0], s[mt][nt][1]));
            mx[mt][1] = fmaxf(mx[mt][1], fmaxf(s[mt][nt][2], s[mt][nt][3]));
        }
#pragma unroll
    for (int mt = 0; mt < 2; mt++)
#pragma unroll
        for (int hi = 0; hi < 2; hi++) {
            float v = mx[mt][hi];
            v = fmaxf(v, __shfl_xor_sync(0xffffffffu, v, 1));
            v = fmaxf(v, __shfl_xor_sync(0xffffffffu, v, 2));
            mx[mt][hi] = v;
        }
    float sum[2][2] = {{0.f, 0.f}, {0.f, 0.f}};
#pragma unroll
    for (int mt = 0; mt < 2; mt++)
#pragma unroll
        for (int nt = 0; nt < 8; nt++) {
#pragma unroll
            for (int e = 0; e < 4; e++) {
                float p = __expf(s[mt][nt][e] - mx[mt][e >> 1]);
                s[mt][nt][e] = p;
                sum[mt][e >> 1] += p;
            }
        }
    float inv[2][2];
#pragma unroll
    for (int mt = 0; mt < 2; mt++)
#pragma unroll
        for (int hi = 0; hi < 2; hi++) {
            float v = sum[mt][hi];
            v += __shfl_xor_sync(0xffffffffu, v, 1);
            v += __shfl_xor_sync(0xffffffffu, v, 2);
            inv[mt][hi] = 1.f / v;
        }

    // ---- all Kt/Qw reads done -> safe to overlay Pw ----
    __syncthreads();

    // ---- P -> smem (tf32, unnormalized) ----
#pragma unroll
    for (int mt = 0; mt < 2; mt++)
#pragma unroll
        for (int nt = 0; nt < 8; nt++) {
            int rlo = (lane >> 2) + 16 * mt;
            int col = 2 * (lane & 3) + 8 * nt;
            uint2 lo = make_uint2(f2tf32(s[mt][nt][0]), f2tf32(s[mt][nt][1]));
            uint2 hi = make_uint2(f2tf32(s[mt][nt][2]), f2tf32(s[mt][nt][3]));
            *reinterpret_cast<uint2*>(&Pw[rlo * 68 + col]) = lo;
            *reinterpret_cast<uint2*>(&Pw[(rlo + 8) * 68 + col]) = hi;
        }
    __syncwarp();

    // ---- O = P V^T ----
    float o[2][4][4];
#pragma unroll
    for (int mt = 0; mt < 2; mt++)
#pragma unroll
        for (int nt = 0; nt < 4; nt++)
#pragma unroll
            for (int e = 0; e < 4; e++) o[mt][nt][e] = 0.f;

#pragma unroll
    for (int kt = 0; kt < 8; kt++) {
        uint32_t a[2][4];
#pragma unroll
        for (int mt = 0; mt < 2; mt++)
#pragma unroll
            for (int sl = 0; sl < 4; sl++) {
                int ir = (lane >> 2) + 8 * (sl & 1) + 16 * mt;
                int jj = (lane & 3) + 4 * (sl >> 1) + 8 * kt;
                a[mt][sl] = Pw[ir * 68 + jj];
            }
#pragma unroll
        for (int nt = 0; nt < 4; nt++) {
            int cc = 8 * nt + (lane >> 2);
            int jb = 8 * kt + (lane & 3);
            uint32_t b0 = Vt[cc * 72 + jb];
            uint32_t b1 = Vt[cc * 72 + jb + 4];
#pragma unroll
            for (int mt = 0; mt < 2; mt++)
                mma_tf32(o[mt][nt][0], o[mt][nt][1], o[mt][nt][2], o[mt][nt][3],
                         a[mt][0], a[mt][1], a[mt][2], a[mt][3], b0, b1);
        }
    }

    // ---- epilogue: scale by 1/rowsum, scatter to g_ao ----
#pragma unroll
    for (int mt = 0; mt < 2; mt++)
#pragma unroll
        for (int nt = 0; nt < 4; nt++)
#pragma unroll
            for (int e = 0; e < 4; e++) {
                int rp  = (lane >> 2) + 8 * (e >> 1) + 16 * mt;
                int tok = w * 32 + rp;
                int cl  = 2 * (lane & 3) + (e & 1) + 8 * nt;
                g_ao[base + (size_t)cl * HW + (size_t)(tok >> 3) * WW2 + (tok & 7)]
                    = o[mt][nt][e] * inv[mt][e >> 1];
            }
}

// ---------------------------------------------------------------------------
extern "C" void kernel_launch(void* const* d_in, const int* in_sizes, int n_in,
                              void* d_out, int out_size)
{
    const float* x  = (const float*)d_in[0];
    const float* Wq = (const float*)d_in[1];
    const float* Wk = (const float*)d_in[2];
    const float* Wv = (const float*)d_in[3];
    const float* Wo = (const float*)d_in[4];
    float* out = (float*)d_out;

    cudaFuncSetAttribute(gemm_multi_kernel,
                         cudaFuncAttributeMaxDynamicSharedMemorySize, SMEM_GEMM_BYTES);

    swz_kernel<<<256, 256>>>(Wq, Wk, Wv, Wo);
    gemm_multi_kernel<<<NTILE, 256, SMEM_GEMM_BYTES>>>(x, 0, nullptr);   // qkv
    attn_tc_kernel<<<BB * NWIN * HEADS, 64>>>();
    gemm_multi_kernel<<<NTILE, 256, SMEM_GEMM_BYTES>>>(x, 1, out);       // wo
}

// round 11
// speedup vs baseline: 1.0113x; 1.0113x over previous
#include <cuda_runtime.h>
#include <cstdint>

#define BB    4
#define CC    256
#define HH    256
#define WW2   256
#define HW    65536          // HH*WW2
#define NPIX  262144         // BB*HW
#define NTILE 2048           // NPIX/128
#define HEADS 8
#define HD    32
#define NWIN  1024           // (HH/8)*(WW2/8)

// Scratch: q, k, v in [B][C][H][W] fp32.
__device__ float g_q [BB * CC * HW];
__device__ float g_k [BB * CC * HW];
__device__ float g_v [BB * CC * HW];

// Fragment-order tf32 B operands in gmem:
//   index = ((ptile*16 + kc)*32 + tile)*64 + lane*2 + sel
//   tile = kt*16 + nt (kt = k-octet within 16-k chunk, nt = pixel-octet)
//   fragment value: sel 0 -> k = kc*16 + kt*8 + (lane&3), sel 1 -> k+4;
//                   pixel p = nt*8 + (lane>>2)  (within the 128-pixel tile)
#define XF_ELEMS ((size_t)NTILE * 16 * 32 * 64)
__device__ uint32_t g_xf [XF_ELEMS];   // projected from x (qkv B operand)
__device__ uint32_t g_aof[XF_ELEMS];   // attention output   (wo  B operand)

// Pre-swizzled weights in mma-fragment order (tf32 bits).
// Layout: [mat(4)][mtile(16)][ktile(32)][lane(32)][slot(4)]
__device__ uint32_t g_swzW[4 * 16 * 32 * 128];

__device__ __forceinline__ uint32_t f2tf32(float f) {
    uint32_t u;
    asm("cvt.rna.tf32.f32 %0, %1;" : "=r"(u) : "f"(f));
    return u;
}

__device__ __forceinline__ void mma_tf32(float& c0, float& c1, float& c2, float& c3,
                                         uint32_t a0, uint32_t a1, uint32_t a2, uint32_t a3,
                                         uint32_t b0, uint32_t b1) {
    asm volatile(
        "mma.sync.aligned.m16n8k8.row.col.f32.tf32.tf32.f32 "
        "{%0,%1,%2,%3}, {%4,%5,%6,%7}, {%8,%9}, {%0,%1,%2,%3};\n"
        : "+f"(c0), "+f"(c1), "+f"(c2), "+f"(c3)
        : "r"(a0), "r"(a1), "r"(a2), "r"(a3), "r"(b0), "r"(b1));
}

// ---------------------------------------------------------------------------
// One-shot weight pre-swizzle: W[m][k] (row-major 256x256) -> fragment order.
// ---------------------------------------------------------------------------
__global__ __launch_bounds__(256) void swz_kernel(const float* __restrict__ Wq,
                                                  const float* __restrict__ Wk,
                                                  const float* __restrict__ Wv,
                                                  const float* __restrict__ Wo)
{
    int idx = blockIdx.x * 256 + threadIdx.x;      // 65536 total
    int lane = idx & 31;
    int kt   = (idx >> 5) & 31;
    int mt   = (idx >> 10) & 15;
    int mat  = idx >> 14;
    const float* W = (mat == 0) ? Wq : (mat == 1) ? Wk : (mat == 2) ? Wv : Wo;

    uint32_t o[4];
#pragma unroll
    for (int s = 0; s < 4; s++) {
        int r = (lane >> 2) + (s & 1) * 8;
        int c = (lane & 3) + (s >> 1) * 4;
        o[s] = f2tf32(W[(mt * 16 + r) * CC + kt * 8 + c]);
    }
    uint4* dst = reinterpret_cast<uint4*>(&g_swzW[(size_t)idx * 4]);
    *dst = make_uint4(o[0], o[1], o[2], o[3]);
}

// ---------------------------------------------------------------------------
// Prepass: x -> g_xf (fragment-order tf32). Block = one (ptile, kc).
// Coalesced float4 LDG -> smem -> fragment gather -> coalesced STG.64.
// ---------------------------------------------------------------------------
__global__ __launch_bounds__(256) void xf_kernel(const float* __restrict__ x)
{
    __shared__ float sm[16 * 132];
    const int tid   = threadIdx.x;
    const int ptile = blockIdx.x >> 4;
    const int kc    = blockIdx.x & 15;
    const int p0    = ptile * 128;
    const int b     = p0 >> 16;
    const int hw0   = p0 & (HW - 1);
    const float* Xb = x + (size_t)b * CC * HW + (size_t)kc * 16 * HW + hw0;

#pragma unroll
    for (int u = 0; u < 2; u++) {
        int f  = tid + u * 256;
        int kk = f >> 5;
        int p4 = (f & 31) * 4;
        float4 v = *reinterpret_cast<const float4*>(Xb + (size_t)kk * HW + p4);
        *reinterpret_cast<float4*>(&sm[kk * 132 + p4]) = v;
    }
    __syncthreads();

    uint32_t* dst = g_xf + ((size_t)ptile * 16 + kc) * 32 * 64;
#pragma unroll
    for (int i = 0; i < 4; i++) {
        int s  = tid + i * 256;
        int t  = s >> 5;
        int ln = s & 31;
        int k  = (t >> 4) * 8 + (ln & 3);
        int p  = (t & 15) * 8 + (ln >> 2);
        uint2 v;
        v.x = f2tf32(sm[k * 132 + p]);
        v.y = f2tf32(sm[(k + 4) * 132 + p]);
        *reinterpret_cast<uint2*>(&dst[t * 64 + ln * 2]) = v;
    }
}

// ---------------------------------------------------------------------------
// tf32 GEMM, B read DIRECTLY from fragment-order gmem (no B smem/cvt/scatter).
// A double-buffered in smem (17 KB). Block tile 128(m) x 128(p).
// ---------------------------------------------------------------------------
__device__ __forceinline__ void gemm_frag(const uint32_t* __restrict__ Wz,
                                          const uint32_t* __restrict__ Xf,
                                          float* __restrict__ Out,
                                          int mBase, int pTile)
{
    __shared__ uint32_t As[2][2112];   // 16 tiles (kt*8+mt) x 132

    const int tid  = threadIdx.x;
    const int w    = tid >> 5;
    const int lane = tid & 31;
    const int wm   = w & 1;
    const int wn   = w >> 1;

    const int p0  = pTile * 128;
    const int b   = p0 >> 16;
    const int hw0 = p0 & (HW - 1);
    float* Ob = Out + (size_t)b * CC * HW + hw0;

    const uint32_t* Xft = Xf + (size_t)pTile * 16 * 32 * 64;

    float acc[4][4][4];
#pragma unroll
    for (int i = 0; i < 4; i++)
#pragma unroll
        for (int j = 0; j < 4; j++)
#pragma unroll
            for (int e = 0; e < 4; e++) acc[i][j][e] = 0.f;

    uint4 aR[2];

    auto ldgA = [&](int kc) {
#pragma unroll
        for (int u = 0; u < 2; u++) {
            int j = tid + u * 256;
            int t = j >> 5;
            int l = j & 31;
            int ktl = t >> 3, mt = t & 7;
            aR[u] = *reinterpret_cast<const uint4*>(
                Wz + ((size_t)mt * 32 + (size_t)(kc * 2 + ktl)) * 128 + l * 4);
        }
    };
    auto stsA = [&](int buf) {
#pragma unroll
        for (int u = 0; u < 2; u++) {
            int j = tid + u * 256;
            int t = j >> 5;
            int l = j & 31;
            *reinterpret_cast<uint4*>(&As[buf][t * 132 + l * 4]) = aR[u];
        }
    };
    auto domma = [&](int buf, int kc) {
        const uint32_t* Bc = Xft + (size_t)kc * 32 * 64;
#pragma unroll
        for (int kt = 0; kt < 2; kt++) {
            uint2 bb[4];
#pragma unroll
            for (int nt = 0; nt < 4; nt++)
                bb[nt] = *reinterpret_cast<const uint2*>(
                    &Bc[(kt * 16 + wn * 4 + nt) * 64 + lane * 2]);
            uint4 a[4];
#pragma unroll
            for (int mt = 0; mt < 4; mt++)
                a[mt] = *reinterpret_cast<const uint4*>(
                    &As[buf][(kt * 8 + wm * 4 + mt) * 132 + lane * 4]);
#pragma unroll
            for (int mt = 0; mt < 4; mt++)
#pragma unroll
                for (int nt = 0; nt < 4; nt++)
                    mma_tf32(acc[mt][nt][0], acc[mt][nt][1], acc[mt][nt][2], acc[mt][nt][3],
                             a[mt].x, a[mt].y, a[mt].z, a[mt].w, bb[nt].x, bb[nt].y);
        }
    };

    ldgA(0);
    stsA(0);
    __syncthreads();
#pragma unroll 1
    for (int kc = 0; kc < 16; kc++) {
        if (kc < 15) ldgA(kc + 1);
        domma(kc & 1, kc);
        if (kc < 15) {
            stsA((kc + 1) & 1);
            __syncthreads();
        }
    }

#pragma unroll
    for (int mt = 0; mt < 4; mt++) {
#pragma unroll
        for (int nt = 0; nt < 4; nt++) {
            int m   = mBase + wm * 64 + mt * 16 + (lane >> 2);
            int col = wn * 32 + nt * 8 + (lane & 3) * 2;
            float* r0 = Ob + (size_t)m * HW + col;
            *reinterpret_cast<float2*>(r0) = make_float2(acc[mt][nt][0], acc[mt][nt][1]);
            *reinterpret_cast<float2*>(r0 + (size_t)8 * HW) =
                make_float2(acc[mt][nt][2], acc[mt][nt][3]);
        }
    }
}

__global__ __launch_bounds__(256, 2) void qkv_kernel()
{
    int mat   = blockIdx.y >> 1;
    int mhalf = blockIdx.y & 1;
    float* Out = (mat == 0) ? g_q : (mat == 1) ? g_k : g_v;
    const uint32_t* Wz = g_swzW + ((size_t)mat * 16 + mhalf * 8) * 32 * 128;
    gemm_frag(Wz, g_xf, Out, mhalf * 128, blockIdx.x);
}

__global__ __launch_bounds__(256, 2) void wo_kernel(float* __restrict__ out)
{
    int mhalf = blockIdx.y;
    const uint32_t* Wz = g_swzW + ((size_t)3 * 16 + mhalf * 8) * 32 * 128;
    gemm_frag(Wz, g_aof, out, mhalf * 128, blockIdx.x);
}

// ---------------------------------------------------------------------------
// Tensor-core windowed attention (R9-proven layout). Block = 64 threads =
// 2 warps = one (window, head). Epilogue writes g_aof in FRAGMENT ORDER so
// wo_kernel needs no prepass.
// ---------------------------------------------------------------------------
__global__ __launch_bounds__(64) void attn_tc_kernel()
{
    __shared__ uint32_t Kt[32 * 72];
    __shared__ uint32_t Vt[32 * 72];
    __shared__ uint32_t Qw[2][32 * 36];
    __shared__ uint32_t Pw[2][32 * 68];

    const int bidx = blockIdx.x;
    const int head = bidx & 7;
    const int win  = bidx >> 3;
    const int b    = win >> 10;
    const int wh   = (win >> 5) & 31;
    const int ww   = win & 31;
    const int tid  = threadIdx.x;
    const int w    = tid >> 5;
    const int lane = tid & 31;

    const size_t base = (size_t)b * CC * HW + (size_t)(head * HD) * HW
                      + (size_t)(wh * 8) * WW2 + (size_t)(ww * 8);

    // ---- load: thread = token j ----
    {
        const int j = tid;
        const size_t off = base + (size_t)(j >> 3) * WW2 + (j & 7);
        const float scale = 0.17677669529663687f;   // 32^-0.5
        const int qsw = ((lane >> 3) & 3) << 3;
#pragma unroll
        for (int c = 0; c < HD; c++) {
            size_t a = off + (size_t)c * HW;
            Kt[c * 72 + j] = f2tf32(g_k[a]);
            Vt[c * 72 + j] = f2tf32(g_v[a]);
            Qw[w][lane * 36 + (c ^ qsw)] = f2tf32(g_q[a] * scale);
        }
    }
    __syncthreads();

    // ---- S = Q^T K ----
    float s[2][8][4];
#pragma unroll
    for (int mt = 0; mt < 2; mt++)
#pragma unroll
        for (int nt = 0; nt < 8; nt++)
#pragma unroll
            for (int e = 0; e < 4; e++) s[mt][nt][e] = 0.f;

#pragma unroll
    for (int kt = 0; kt < 4; kt++) {
        uint32_t a[2][4];
#pragma unroll
        for (int mt = 0; mt < 2; mt++)
#pragma unroll
            for (int sl = 0; sl < 4; sl++) {
                int ir = (lane >> 2) + 8 * (sl & 1) + 16 * mt;
                int c  = (lane & 3) + 4 * (sl >> 1) + 8 * kt;
                int ks = ((ir >> 3) & 3) << 3;
                a[mt][sl] = Qw[w][ir * 36 + (c ^ ks)];
            }
#pragma unroll
        for (int nt = 0; nt < 8; nt++) {
            int cb = 8 * kt + (lane & 3);
            int jj = 8 * nt + (lane >> 2);
            uint32_t b0 = Kt[cb * 72 + jj];
            uint32_t b1 = Kt[(cb + 4) * 72 + jj];
#pragma unroll
            for (int mt = 0; mt < 2; mt++)
                mma_tf32(s[mt][nt][0], s[mt][nt][1], s[mt][nt][2], s[mt][nt][3],
                         a[mt][0], a[mt][1], a[mt][2], a[mt][3], b0, b1);
        }
    }

    // ---- softmax ----
    float mx[2][2] = {{-1e30f, -1e30f}, {-1e30f, -1e30f}};
#pragma unroll
    for (int mt = 0; mt < 2; mt++)
#pragma unroll
        for (int nt = 0; nt < 8; nt++) {
            mx[mt][0] = fmaxf(mx[mt][0], fmaxf(s[mt][nt][0], s[mt][nt][1]));
            mx[mt][1] = fmaxf(mx[mt][1], fmaxf(s[mt][nt][2], s[mt][nt][3]));
        }
#pragma unroll
    for (int mt = 0; mt < 2; mt++)
#pragma unroll
        for (int hi = 0; hi < 2; hi++) {
            float v = mx[mt][hi];
            v = fmaxf(v, __shfl_xor_sync(0xffffffffu, v, 1));
            v = fmaxf(v, __shfl_xor_sync(0xffffffffu, v, 2));
            mx[mt][hi] = v;
        }
    float sum[2][2] = {{0.f, 0.f}, {0.f, 0.f}};
#pragma unroll
    for (int mt = 0; mt < 2; mt++)
#pragma unroll
        for (int nt = 0; nt < 8; nt++) {
#pragma unroll
            for (int e = 0; e < 4; e++) {
                float p = __expf(s[mt][nt][e] - mx[mt][e >> 1]);
                s[mt][nt][e] = p;
                sum[mt][e >> 1] += p;
            }
        }
    float inv[2][2];
#pragma unroll
    for (int mt = 0; mt < 2; mt++)
#pragma unroll
        for (int hi = 0; hi < 2; hi++) {
            float v = sum[mt][hi];
            v += __shfl_xor_sync(0xffffffffu, v, 1);
            v += __shfl_xor_sync(0xffffffffu, v, 2);
            inv[mt][hi] = 1.f / v;
        }

    // ---- P -> smem (tf32, unnormalized) ----
#pragma unroll
    for (int mt = 0; mt < 2; mt++)
#pragma unroll
        for (int nt = 0; nt < 8; nt++) {
            int rlo = (lane >> 2) + 16 * mt;
            int col = 2 * (lane & 3) + 8 * nt;
            uint2 lo = make_uint2(f2tf32(s[mt][nt][0]), f2tf32(s[mt][nt][1]));
            uint2 hi = make_uint2(f2tf32(s[mt][nt][2]), f2tf32(s[mt][nt][3]));
            *reinterpret_cast<uint2*>(&Pw[w][rlo * 68 + col]) = lo;
            *reinterpret_cast<uint2*>(&Pw[w][(rlo + 8) * 68 + col]) = hi;
        }
    __syncwarp();

    // ---- O = P V^T ----
    float o[2][4][4];
#pragma unroll
    for (int mt = 0; mt < 2; mt++)
#pragma unroll
        for (int nt = 0; nt < 4; nt++)
#pragma unroll
            for (int e = 0; e < 4; e++) o[mt][nt][e] = 0.f;

#pragma unroll
    for (int kt = 0; kt < 8; kt++) {
        uint32_t a[2][4];
#pragma unroll
        for (int mt = 0; mt < 2; mt++)
#pragma unroll
            for (int sl = 0; sl < 4; sl++) {
                int ir = (lane >> 2) + 8 * (sl & 1) + 16 * mt;
                int jj = (lane & 3) + 4 * (sl >> 1) + 8 * kt;
                a[mt][sl] = Pw[w][ir * 68 + jj];
            }
#pragma unroll
        for (int nt = 0; nt < 4; nt++) {
            int cc = 8 * nt + (lane >> 2);
            int jb = 8 * kt + (lane & 3);
            uint32_t b0 = Vt[cc * 72 + jb];
            uint32_t b1 = Vt[cc * 72 + jb + 4];
#pragma unroll
            for (int mt = 0; mt < 2; mt++)
                mma_tf32(o[mt][nt][0], o[mt][nt][1], o[mt][nt][2], o[mt][nt][3],
                         a[mt][0], a[mt][1], a[mt][2], a[mt][3], b0, b1);
        }
    }

    // ---- epilogue: scale by 1/rowsum, write FRAGMENT-ORDER tf32 to g_aof ----
#pragma unroll
    for (int mt = 0; mt < 2; mt++)
#pragma unroll
        for (int nt = 0; nt < 4; nt++)
#pragma unroll
            for (int e = 0; e < 4; e++) {
                int rp  = (lane >> 2) + 8 * (e >> 1) + 16 * mt;
                int tok = w * 32 + rp;
                int cl  = 2 * (lane & 3) + (e & 1) + 8 * nt;
                int k   = head * HD + cl;
                int P   = b * HW + (wh * 8 + (tok >> 3)) * WW2 + ww * 8 + (tok & 7);
                int pt  = P >> 7;
                int pp  = P & 127;
                int ln2 = (pp & 7) * 4 + (k & 3);
                size_t idx = (((size_t)pt * 16 + (k >> 4)) * 32
                              + ((k >> 3) & 1) * 16 + (pp >> 3)) * 64
                             + ln2 * 2 + ((k >> 2) & 1);
                g_aof[idx] = f2tf32(o[mt][nt][e] * inv[mt][e >> 1]);
            }
}

// ---------------------------------------------------------------------------
extern "C" void kernel_launch(void* const* d_in, const int* in_sizes, int n_in,
                              void* d_out, int out_size)
{
    const float* x  = (const float*)d_in[0];
    const float* Wq = (const float*)d_in[1];
    const float* Wk = (const float*)d_in[2];
    const float* Wv = (const float*)d_in[3];
    const float* Wo = (const float*)d_in[4];
    float* out = (float*)d_out;

    swz_kernel<<<256, 256>>>(Wq, Wk, Wv, Wo);
    xf_kernel<<<NTILE * 16, 256>>>(x);
    qkv_kernel<<<dim3(NTILE, 6), 256>>>();
    attn_tc_kernel<<<BB * NWIN * HEADS, 64>>>();
    wo_kernel<<<dim3(NTILE, 2), 256>>>(out);
}

// round 12
// speedup vs baseline: 1.2135x; 1.1999x over previous
#include <cuda_runtime.h>
#include <cstdint>

#define BB    4
#define CC    256
#define HH    256
#define WW2   256
#define HW    65536          // HH*WW2
#define NPIX  262144         // BB*HW
#define NTILE 2048           // NPIX/128
#define HEADS 8
#define HD    32
#define NWIN  1024           // (HH/8)*(WW2/8)

// q, k, v in WINDOW layout: [(b*NWIN+win)*HEADS + head][c(32)][tok(64)]
__device__ float g_q [BB * CC * HW];
__device__ float g_k [BB * CC * HW];
__device__ float g_v [BB * CC * HW];
// attention output in [B][C][H][W] (input layout for wo GEMM)
__device__ float g_ao[BB * CC * HW];

// Pre-swizzled weights in mma-fragment order (tf32 bits).
// Layout: [mat(4)][mtile(16)][ktile(32)][lane(32)][slot(4)]
__device__ uint32_t g_swzW[4 * 16 * 32 * 128];

__device__ __forceinline__ uint32_t f2tf32(float f) {
    uint32_t u;
    asm("cvt.rna.tf32.f32 %0, %1;" : "=r"(u) : "f"(f));
    return u;
}

__device__ __forceinline__ void mma_tf32(float& c0, float& c1, float& c2, float& c3,
                                         uint32_t a0, uint32_t a1, uint32_t a2, uint32_t a3,
                                         uint32_t b0, uint32_t b1) {
    asm volatile(
        "mma.sync.aligned.m16n8k8.row.col.f32.tf32.tf32.f32 "
        "{%0,%1,%2,%3}, {%4,%5,%6,%7}, {%8,%9}, {%0,%1,%2,%3};\n"
        : "+f"(c0), "+f"(c1), "+f"(c2), "+f"(c3)
        : "r"(a0), "r"(a1), "r"(a2), "r"(a3), "r"(b0), "r"(b1));
}

// ---------------------------------------------------------------------------
// One-shot weight pre-swizzle: W[m][k] (row-major 256x256) -> fragment order.
// ---------------------------------------------------------------------------
__global__ __launch_bounds__(256) void swz_kernel(const float* __restrict__ Wq,
                                                  const float* __restrict__ Wk,
                                                  const float* __restrict__ Wv,
                                                  const float* __restrict__ Wo)
{
    int idx = blockIdx.x * 256 + threadIdx.x;      // 65536 total
    int lane = idx & 31;
    int kt   = (idx >> 5) & 31;
    int mt   = (idx >> 10) & 15;
    int mat  = idx >> 14;
    const float* W = (mat == 0) ? Wq : (mat == 1) ? Wk : (mat == 2) ? Wv : Wo;

    uint32_t o[4];
#pragma unroll
    for (int s = 0; s < 4; s++) {
        int r = (lane >> 2) + (s & 1) * 8;
        int c = (lane & 3) + (s >> 1) * 4;
        o[s] = f2tf32(W[(mt * 16 + r) * CC + kt * 8 + c]);
    }
    uint4* dst = reinterpret_cast<uint4*>(&g_swzW[(size_t)idx * 4]);
    *dst = make_uint4(o[0], o[1], o[2], o[3]);
}

// ---------------------------------------------------------------------------
// tf32 tensor-core GEMM (R9-proven): Out[m, p] = sum_k W[m, k] * X[k, p]
// Block tile 128(m) x 128(p), K-chunk 16, double-buffered, de-conflicted stsB.
// winout=1: scatter output to window layout [(b*NWIN+win)*8+head][c][tok].
// ---------------------------------------------------------------------------
__device__ __forceinline__ void gemm_tc(const uint32_t* __restrict__ Wz,
                                        const float* __restrict__ X,
                                        float* __restrict__ Out,
                                        int mBase, int pTile, int winout)
{
    __shared__ uint32_t As[2][2112];   // 16 tiles (kt*8+mt) x 132
    __shared__ uint32_t Bs[2][2112];   // 32 tiles (kt*16+nt) x 66

    const int tid  = threadIdx.x;
    const int w    = tid >> 5;
    const int lane = tid & 31;
    const int wm   = w & 1;
    const int wn   = w >> 1;

    const int p0  = pTile * 128;
    const int b   = p0 >> 16;
    const int hw0 = p0 & (HW - 1);
    const float* Xb = X   + (size_t)b * CC * HW + hw0;
    float*       Ob = Out + (size_t)b * CC * HW + hw0;

    float acc[4][4][4];
#pragma unroll
    for (int i = 0; i < 4; i++)
#pragma unroll
        for (int j = 0; j < 4; j++)
#pragma unroll
            for (int e = 0; e < 4; e++) acc[i][j][e] = 0.f;

    uint4  aR[2];
    float4 bR[2];

    auto ldgA = [&](int kc) {
#pragma unroll
        for (int u = 0; u < 2; u++) {
            int j = tid + u * 256;
            int t = j >> 5;
            int l = j & 31;
            int ktl = t >> 3, mt = t & 7;
            aR[u] = *reinterpret_cast<const uint4*>(
                Wz + ((size_t)mt * 32 + (size_t)(kc * 2 + ktl)) * 128 + l * 4);
        }
    };
    auto stsA = [&](int buf) {
#pragma unroll
        for (int u = 0; u < 2; u++) {
            int j = tid + u * 256;
            int t = j >> 5;
            int l = j & 31;
            *reinterpret_cast<uint4*>(&As[buf][t * 132 + l * 4]) = aR[u];
        }
    };
    auto ldgB = [&](int kc) {
#pragma unroll
        for (int u = 0; u < 2; u++) {
            int j  = tid + u * 256;
            int wj = j >> 5;
            int l  = j & 31;
            int h  = l >> 4;
            int m  = l & 15;
            int k  = 2 * (wj & 7) + h;
            int pf = ((wj >> 3) * 16 + m) * 4;
            bR[u] = *reinterpret_cast<const float4*>(Xb + (size_t)(kc * 16 + k) * HW + pf);
        }
    };
    auto stsB = [&](int buf) {
#pragma unroll
        for (int u = 0; u < 2; u++) {
            int j  = tid + u * 256;
            int wj = j >> 5;
            int l  = j & 31;
            int h  = l >> 4;
            int m  = l & 15;
            int k  = 2 * (wj & 7) + h;
            int pf = ((wj >> 3) * 16 + m) * 4;
            int ktl = k >> 3, ch = k & 7;
            int slot = ch >> 2, cl = ch & 3;
            int sl2 = slot ^ (cl & 1);
            float vals[4] = {bR[u].x, bR[u].y, bR[u].z, bR[u].w};
#pragma unroll
            for (int e = 0; e < 4; e++) {
                int p  = pf + e;
                int nt = p >> 3;
                int n  = p & 7;
                int off = (n * 4 + cl) * 2 + sl2;
                off ^= (n & 4) << 2;              // intra-tile swizzle only
                Bs[buf][(ktl * 16 + nt) * 66 + off] = f2tf32(vals[e]);
            }
        }
    };
    const int blx = (lane * 2) ^ (lane & 16);
    const bool bswap = (lane & 1);
    auto domma = [&](int buf) {
#pragma unroll
        for (int kt = 0; kt < 2; kt++) {
            uint4 a[4];
            uint32_t b0[4], b1[4];
#pragma unroll
            for (int mt = 0; mt < 4; mt++)
                a[mt] = *reinterpret_cast<const uint4*>(
                    &As[buf][(kt * 8 + wm * 4 + mt) * 132 + lane * 4]);
#pragma unroll
            for (int nt = 0; nt < 4; nt++) {
                uint2 raw = *reinterpret_cast<const uint2*>(
                    &Bs[buf][(kt * 16 + wn * 4 + nt) * 66 + blx]);
                b0[nt] = bswap ? raw.y : raw.x;
                b1[nt] = bswap ? raw.x : raw.y;
            }
#pragma unroll
            for (int mt = 0; mt < 4; mt++)
#pragma unroll
                for (int nt = 0; nt < 4; nt++)
                    mma_tf32(acc[mt][nt][0], acc[mt][nt][1], acc[mt][nt][2], acc[mt][nt][3],
                             a[mt].x, a[mt].y, a[mt].z, a[mt].w, b0[nt], b1[nt]);
        }
    };

    ldgA(0); ldgB(0);
    stsA(0); stsB(0);
    __syncthreads();
#pragma unroll 1
    for (int kc = 0; kc < 16; kc++) {
        if (kc < 15) { ldgA(kc + 1); ldgB(kc + 1); }
        domma(kc & 1);
        if (kc < 15) {
            stsA((kc + 1) & 1); stsB((kc + 1) & 1);
            __syncthreads();
        }
    }

    if (winout) {
        // window layout: [(b*NWIN + win)*8 + head][c][tok]
#pragma unroll
        for (int mt = 0; mt < 4; mt++) {
#pragma unroll
            for (int nt = 0; nt < 4; nt++) {
                int m0  = mBase + wm * 64 + mt * 16 + (lane >> 2);
                int col = wn * 32 + nt * 8 + (lane & 3) * 2;
                int hw  = hw0 + col;
                int h   = hw >> 8;
                int wp  = hw & 255;
                int win = ((h >> 3) << 5) | (wp >> 3);
                int tok = ((h & 7) << 3) | (wp & 7);
                size_t wbase = ((size_t)(b * NWIN + win)) * 16384 + (size_t)tok;
#pragma unroll
                for (int rr = 0; rr < 2; rr++) {
                    int mm = m0 + rr * 8;
                    float* dst = Out + wbase + (size_t)(mm >> 5) * 2048
                                     + (size_t)(mm & 31) * 64;
                    *reinterpret_cast<float2*>(dst) =
                        make_float2(acc[mt][nt][rr * 2], acc[mt][nt][rr * 2 + 1]);
                }
            }
        }
    } else {
#pragma unroll
        for (int mt = 0; mt < 4; mt++) {
#pragma unroll
            for (int nt = 0; nt < 4; nt++) {
                int m   = mBase + wm * 64 + mt * 16 + (lane >> 2);
                int col = wn * 32 + nt * 8 + (lane & 3) * 2;
                float* r0 = Ob + (size_t)m * HW + col;
                *reinterpret_cast<float2*>(r0) = make_float2(acc[mt][nt][0], acc[mt][nt][1]);
                *reinterpret_cast<float2*>(r0 + (size_t)8 * HW) =
                    make_float2(acc[mt][nt][2], acc[mt][nt][3]);
            }
        }
    }
}

__global__ __launch_bounds__(256, 2) void qkv_kernel(const float* __restrict__ x)
{
    int mat   = blockIdx.y >> 1;
    int mhalf = blockIdx.y & 1;
    float* Out = (mat == 0) ? g_q : (mat == 1) ? g_k : g_v;
    const uint32_t* Wz = g_swzW + ((size_t)mat * 16 + mhalf * 8) * 32 * 128;
    gemm_tc(Wz, x, Out, mhalf * 128, blockIdx.x, 1);
}

__global__ __launch_bounds__(256, 2) void wo_kernel(float* __restrict__ out)
{
    int mhalf = blockIdx.y;
    const uint32_t* Wz = g_swzW + ((size_t)3 * 16 + mhalf * 8) * 32 * 128;
    gemm_tc(Wz, g_ao, out, mhalf * 128, blockIdx.x, 0);
}

// ---------------------------------------------------------------------------
// Tensor-core windowed attention. Block = 64 threads = 2 warps = one
// (window, head); q/k/v come in WINDOW layout so every load is coalesced.
// Smem 27 KB: Vt[2304]; KQ[4608] = Kt | Qw during S phase, reused as Pw
// after a __syncthreads() (all Kt/Qw reads complete by then).
// ---------------------------------------------------------------------------
__global__ __launch_bounds__(64) void attn_tc_kernel()
{
    __shared__ uint32_t Vt[32 * 72];     // 2304
    __shared__ uint32_t KQ[4608];        // Kt | Qw -> later Pw

    const int bidx = blockIdx.x;         // (b*NWIN + win)*8 + head
    const int head = bidx & 7;
    const int win  = bidx >> 3;          // global: b*NWIN + winLocal
    const int b    = win >> 10;
    const int wh   = (win >> 5) & 31;
    const int ww   = win & 31;
    const int tid  = threadIdx.x;
    const int w    = tid >> 5;
    const int lane = tid & 31;

    uint32_t* Kt = KQ;
    uint32_t* Qw = KQ + 2304 + w * 1152;   // stride-36 rows
    uint32_t* Pw = KQ + w * 2176;          // stride-68 rows (valid after sync)

    const size_t src = (size_t)bidx * 2048;          // window-layout base
    const size_t obase = (size_t)b * CC * HW + (size_t)(head * HD) * HW
                       + (size_t)(wh * 8) * WW2 + (size_t)(ww * 8);

    // ---- load (coalesced: lanes = consecutive tokens) ----
    {
        const int j = tid;
        const float scale = 0.17677669529663687f;   // 32^-0.5
        const int qsw = ((lane >> 3) & 3) << 3;
#pragma unroll
        for (int c = 0; c < HD; c++) {
            size_t a = src + (size_t)c * 64 + j;
            Kt[c * 72 + j] = f2tf32(g_k[a]);
            Vt[c * 72 + j] = f2tf32(g_v[a]);
            Qw[lane * 36 + (c ^ qsw)] = f2tf32(g_q[a] * scale);
        }
    }
    __syncthreads();

    // ---- S = Q^T K ----
    float s[2][8][4];
#pragma unroll
    for (int mt = 0; mt < 2; mt++)
#pragma unroll
        for (int nt = 0; nt < 8; nt++)
#pragma unroll
            for (int e = 0; e < 4; e++) s[mt][nt][e] = 0.f;

#pragma unroll
    for (int kt = 0; kt < 4; kt++) {
        uint32_t a[2][4];
#pragma unroll
        for (int mt = 0; mt < 2; mt++)
#pragma unroll
            for (int sl = 0; sl < 4; sl++) {
                int ir = (lane >> 2) + 8 * (sl & 1) + 16 * mt;
                int c  = (lane & 3) + 4 * (sl >> 1) + 8 * kt;
                int ks = ((ir >> 3) & 3) << 3;
                a[mt][sl] = Qw[ir * 36 + (c ^ ks)];
            }
#pragma unroll
        for (int nt = 0; nt < 8; nt++) {
            int cb = 8 * kt + (lane & 3);
            int jj = 8 * nt + (lane >> 2);
            uint32_t b0 = Kt[cb * 72 + jj];
            uint32_t b1 = Kt[(cb + 4) * 72 + jj];
#pragma unroll
            for (int mt = 0; mt < 2; mt++)
                mma_tf32(s[mt][nt][0], s[mt][nt][1], s[mt][nt][2], s[mt][nt][3],
                         a[mt][0], a[mt][1], a[mt][2], a[mt][3], b0, b1);
        }
    }

    // ---- softmax (register-only, quad shuffles) ----
    float mx[2][2] = {{-1e30f, -1e30f}, {-1e30f, -1e30f}};
#pragma unroll
    for (int mt = 0; mt < 2; mt++)
#pragma unroll
        for (int nt = 0; nt < 8; nt++) {
            mx[mt][0] = fmaxf(mx[mt][0], fmaxf(s[mt][nt][0], s[mt][nt][1]));
            mx[mt][1] = fmaxf(mx[mt][1], fmaxf(s[mt][nt][2], s[mt][nt][3]));
        }
#pragma unroll
    for (int mt = 0; mt < 2; mt++)
#pragma unroll
        for (int hi = 0; hi < 2; hi++) {
            float v = mx[mt][hi];
            v = fmaxf(v, __shfl_xor_sync(0xffffffffu, v, 1));
            v = fmaxf(v, __shfl_xor_sync(0xffffffffu, v, 2));
            mx[mt][hi] = v;
        }
    float sum[2][2] = {{0.f, 0.f}, {0.f, 0.f}};
#pragma unroll
    for (int mt = 0; mt < 2; mt++)
#pragma unroll
        for (int nt = 0; nt < 8; nt++) {
#pragma unroll
            for (int e = 0; e < 4; e++) {
                float p = __expf(s[mt][nt][e] - mx[mt][e >> 1]);
                s[mt][nt][e] = p;
                sum[mt][e >> 1] += p;
            }
        }
    float inv[2][2];
#pragma unroll
    for (int mt = 0; mt < 2; mt++)
#pragma unroll
        for (int hi = 0; hi < 2; hi++) {
            float v = sum[mt][hi];
            v += __shfl_xor_sync(0xffffffffu, v, 1);
            v += __shfl_xor_sync(0xffffffffu, v, 2);
            inv[mt][hi] = 1.f / v;
        }

    // ---- all Kt/Qw reads done -> safe to overlay Pw ----
    __syncthreads();

    // ---- P -> smem (tf32, unnormalized) ----
#pragma unroll
    for (int mt = 0; mt < 2; mt++)
#pragma unroll
        for (int nt = 0; nt < 8; nt++) {
            int rlo = (lane >> 2) + 16 * mt;
            int col = 2 * (lane & 3) + 8 * nt;
            uint2 lo = make_uint2(f2tf32(s[mt][nt][0]), f2tf32(s[mt][nt][1]));
            uint2 hi = make_uint2(f2tf32(s[mt][nt][2]), f2tf32(s[mt][nt][3]));
            *reinterpret_cast<uint2*>(&Pw[rlo * 68 + col]) = lo;
            *reinterpret_cast<uint2*>(&Pw[(rlo + 8) * 68 + col]) = hi;
        }
    __syncwarp();

    // ---- O = P V^T ----
    float o[2][4][4];
#pragma unroll
    for (int mt = 0; mt < 2; mt++)
#pragma unroll
        for (int nt = 0; nt < 4; nt++)
#pragma unroll
            for (int e = 0; e < 4; e++) o[mt][nt][e] = 0.f;

#pragma unroll
    for (int kt = 0; kt < 8; kt++) {
        uint32_t a[2][4];
#pragma unroll
        for (int mt = 0; mt < 2; mt++)
#pragma unroll
            for (int sl = 0; sl < 4; sl++) {
                int ir = (lane >> 2) + 8 * (sl & 1) + 16 * mt;
                int jj = (lane & 3) + 4 * (sl >> 1) + 8 * kt;
                a[mt][sl] = Pw[ir * 68 + jj];
            }
#pragma unroll
        for (int nt = 0; nt < 4; nt++) {
            int cc = 8 * nt + (lane >> 2);
            int jb = 8 * kt + (lane & 3);
            uint32_t b0 = Vt[cc * 72 + jb];
            uint32_t b1 = Vt[cc * 72 + jb + 4];
#pragma unroll
            for (int mt = 0; mt < 2; mt++)
                mma_tf32(o[mt][nt][0], o[mt][nt][1], o[mt][nt][2], o[mt][nt][3],
                         a[mt][0], a[mt][1], a[mt][2], a[mt][3], b0, b1);
        }
    }

    // ---- epilogue: scale by 1/rowsum, scatter to g_ao [B][C][HW] ----
#pragma unroll
    for (int mt = 0; mt < 2; mt++)
#pragma unroll
        for (int nt = 0; nt < 4; nt++)
#pragma unroll
            for (int e = 0; e < 4; e++) {
                int rp  = (lane >> 2) + 8 * (e >> 1) + 16 * mt;
                int tok = w * 32 + rp;
                int cl  = 2 * (lane & 3) + (e & 1) + 8 * nt;
                g_ao[obase + (size_t)cl * HW + (size_t)(tok >> 3) * WW2 + (tok & 7)]
                    = o[mt][nt][e] * inv[mt][e >> 1];
            }
}

// ---------------------------------------------------------------------------
extern "C" void kernel_launch(void* const* d_in, const int* in_sizes, int n_in,
                              void* d_out, int out_size)
{
    const float* x  = (const float*)d_in[0];
    const float* Wq = (const float*)d_in[1];
    const float* Wk = (const float*)d_in[2];
    const float* Wv = (const float*)d_in[3];
    const float* Wo = (const float*)d_in[4];
    float* out = (float*)d_out;

    swz_kernel<<<256, 256>>>(Wq, Wk, Wv, Wo);
    qkv_kernel<<<dim3(NTILE, 6), 256>>>(x);
    attn_tc_kernel<<<BB * NWIN * HEADS, 64>>>();
    wo_kernel<<<dim3(NTILE, 2), 256>>>(out);
}

// round 13
// speedup vs baseline: 1.6686x; 1.3750x over previous
#include <cuda_runtime.h>
#include <cuda_fp16.h>
#include <cstdint>

#define BB    4
#define CC    256
#define HH    256
#define WW2   256
#define HW    65536          // HH*WW2
#define NPIX  262144         // BB*HW
#define NTILE 2048           // NPIX/128
#define HEADS 8
#define HD    32
#define NWIN  1024           // (HH/8)*(WW2/8)

// q, k, v in WINDOW layout: [(b*NWIN+win)*HEADS + head][c(32)][tok(64)]
__device__ float g_q [BB * CC * HW];
__device__ float g_k [BB * CC * HW];
__device__ float g_v [BB * CC * HW];
// attention output in [B][C][H][W] (input layout for wo GEMM)
__device__ float g_ao[BB * CC * HW];

// Pre-swizzled weights as fp16 m16n8k16 A fragments.
// Layout: [mat(4)][mtile(16)][ktile(16)][lane(32)][reg(4)]  (u32 = half2)
__device__ uint32_t g_swzW[4 * 16 * 16 * 128];

__device__ __forceinline__ uint32_t f2tf32(float f) {
    uint32_t u;
    asm("cvt.rna.tf32.f32 %0, %1;" : "=r"(u) : "f"(f));
    return u;
}

__device__ __forceinline__ uint32_t pack_h2(float lo, float hi) {
    __half2 h = __floats2half2_rn(lo, hi);
    return *reinterpret_cast<uint32_t*>(&h);
}

// B smem intra-tile swizzle: write/read mirror, conflict-free both sides.
__device__ __forceinline__ int swzB(int l) {
    return (l * 2) ^ (((l >> 4) & 1) << 3);
}

__device__ __forceinline__ void mma_f16(float& c0, float& c1, float& c2, float& c3,
                                        uint32_t a0, uint32_t a1, uint32_t a2, uint32_t a3,
                                        uint32_t b0, uint32_t b1) {
    asm volatile(
        "mma.sync.aligned.m16n8k16.row.col.f32.f16.f16.f32 "
        "{%0,%1,%2,%3}, {%4,%5,%6,%7}, {%8,%9}, {%0,%1,%2,%3};\n"
        : "+f"(c0), "+f"(c1), "+f"(c2), "+f"(c3)
        : "r"(a0), "r"(a1), "r"(a2), "r"(a3), "r"(b0), "r"(b1));
}

__device__ __forceinline__ void mma_tf32(float& c0, float& c1, float& c2, float& c3,
                                         uint32_t a0, uint32_t a1, uint32_t a2, uint32_t a3,
                                         uint32_t b0, uint32_t b1) {
    asm volatile(
        "mma.sync.aligned.m16n8k8.row.col.f32.tf32.tf32.f32 "
        "{%0,%1,%2,%3}, {%4,%5,%6,%7}, {%8,%9}, {%0,%1,%2,%3};\n"
        : "+f"(c0), "+f"(c1), "+f"(c2), "+f"(c3)
        : "r"(a0), "r"(a1), "r"(a2), "r"(a3), "r"(b0), "r"(b1));
}

// ---------------------------------------------------------------------------
// One-shot weight pre-swizzle: W[m][k] -> fp16 m16n8k16 A-fragment order.
// reg s: row = g + 8*(s&1), cols = 2t + 8*(s>>1) + {0,1}  (g=lane>>2, t=lane&3)
// ---------------------------------------------------------------------------
__global__ __launch_bounds__(256) void swz_kernel(const float* __restrict__ Wq,
                                                  const float* __restrict__ Wk,
                                                  const float* __restrict__ Wv,
                                                  const float* __restrict__ Wo)
{
    int idx = blockIdx.x * 256 + threadIdx.x;      // 32768 total
    int lane = idx & 31;
    int kt   = (idx >> 5) & 15;
    int mt   = (idx >> 9) & 15;
    int mat  = idx >> 13;
    const float* W = (mat == 0) ? Wq : (mat == 1) ? Wk : (mat == 2) ? Wv : Wo;

    uint32_t o[4];
#pragma unroll
    for (int s = 0; s < 4; s++) {
        int r = mt * 16 + (lane >> 2) + 8 * (s & 1);
        int c = kt * 16 + 2 * (lane & 3) + 8 * (s >> 1);
        o[s] = pack_h2(W[r * CC + c], W[r * CC + c + 1]);
    }
    *reinterpret_cast<uint4*>(&g_swzW[(size_t)idx * 4]) = make_uint4(o[0], o[1], o[2], o[3]);
}

// ---------------------------------------------------------------------------
// fp16 tensor-core GEMM: Out[m, p] = sum_k W[m, k] * X[k, p]
// Block tile 128(m) x 128(p), K-chunk 32 (2 k16 subtiles), double-buffered.
// winout=1: scatter output to window layout [(b*NWIN+win)*8+head][c][tok].
// ---------------------------------------------------------------------------
__device__ __forceinline__ void gemm_tc(const uint32_t* __restrict__ Wz,
                                        const float* __restrict__ X,
                                        float* __restrict__ Out,
                                        int mBase, int pTile, int winout)
{
    __shared__ alignas(16) uint32_t As[2][2112];   // 16 tiles (kt2*8+mt) x 132
    __shared__ alignas(16) uint32_t Bs[2][2112];   // 32 tiles (kt2*16+nt) x 66

    const int tid  = threadIdx.x;
    const int w    = tid >> 5;
    const int lane = tid & 31;
    const int wm   = w & 1;
    const int wn   = w >> 1;

    const int p0  = pTile * 128;
    const int b   = p0 >> 16;
    const int hw0 = p0 & (HW - 1);
    const float* Xb = X   + (size_t)b * CC * HW + hw0;
    float*       Ob = Out + (size_t)b * CC * HW + hw0;

    float acc[4][4][4];
#pragma unroll
    for (int i = 0; i < 4; i++)
#pragma unroll
        for (int j = 0; j < 4; j++)
#pragma unroll
            for (int e = 0; e < 4; e++) acc[i][j][e] = 0.f;

    uint4  aR[2];
    float2 bR[2][4];      // [kt2][row: 2t,2t+1,2t+8,2t+9]

    const int tq = tid >> 6;        // 0..3 : k-pair group
    const int p2 = tid & 63;        // pixel pair

    auto ldgA = [&](int kc) {       // kc in 0..7, covers k-tiles kc*2, kc*2+1
#pragma unroll
        for (int u = 0; u < 2; u++) {
            int j = tid + u * 256;
            int t = j >> 5;                 // kt2*8 + mt
            int l = j & 31;
            int kt2 = t >> 3, mt = t & 7;
            aR[u] = *reinterpret_cast<const uint4*>(
                Wz + ((size_t)mt * 16 + (size_t)(kc * 2 + kt2)) * 128 + l * 4);
        }
    };
    auto stsA = [&](int buf) {
#pragma unroll
        for (int u = 0; u < 2; u++) {
            int j = tid + u * 256;
            int t = j >> 5;
            int l = j & 31;
            *reinterpret_cast<uint4*>(&As[buf][t * 132 + l * 4]) = aR[u];
        }
    };
    auto ldgB = [&](int kc) {
#pragma unroll
        for (int kt2 = 0; kt2 < 2; kt2++) {
            int kb = kc * 32 + kt2 * 16;
#pragma unroll
            for (int r = 0; r < 4; r++) {
                int krow = kb + 2 * tq + (r & 1) + 8 * (r >> 1);   // 2t,2t+1,2t+8,2t+9
                bR[kt2][r] = *reinterpret_cast<const float2*>(
                    Xb + (size_t)krow * HW + p2 * 2);
            }
        }
    };
    auto stsB = [&](int buf) {
#pragma unroll
        for (int kt2 = 0; kt2 < 2; kt2++) {
#pragma unroll
            for (int e = 0; e < 2; e++) {
                int p = 2 * p2 + e;
                float v0 = e ? bR[kt2][0].y : bR[kt2][0].x;   // row 2t
                float v1 = e ? bR[kt2][1].y : bR[kt2][1].x;   // row 2t+1
                float v2 = e ? bR[kt2][2].y : bR[kt2][2].x;   // row 2t+8
                float v3 = e ? bR[kt2][3].y : bR[kt2][3].x;   // row 2t+9
                uint2 regs = make_uint2(pack_h2(v0, v1), pack_h2(v2, v3));
                int tile = kt2 * 16 + (p >> 3);
                int l    = (p & 7) * 4 + tq;
                *reinterpret_cast<uint2*>(&Bs[buf][tile * 66 + swzB(l)]) = regs;
            }
        }
    };
    const int swzlane = swzB(lane);
    auto domma = [&](int buf) {
#pragma unroll
        for (int kt2 = 0; kt2 < 2; kt2++) {
            uint4 a[4];
            uint2 bb[4];
#pragma unroll
            for (int mt = 0; mt < 4; mt++)
                a[mt] = *reinterpret_cast<const uint4*>(
                    &As[buf][(kt2 * 8 + wm * 4 + mt) * 132 + lane * 4]);
#pragma unroll
            for (int nt = 0; nt < 4; nt++)
                bb[nt] = *reinterpret_cast<const uint2*>(
                    &Bs[buf][(kt2 * 16 + wn * 4 + nt) * 66 + swzlane]);
#pragma unroll
            for (int mt = 0; mt < 4; mt++)
#pragma unroll
                for (int nt = 0; nt < 4; nt++)
                    mma_f16(acc[mt][nt][0], acc[mt][nt][1], acc[mt][nt][2], acc[mt][nt][3],
                            a[mt].x, a[mt].y, a[mt].z, a[mt].w, bb[nt].x, bb[nt].y);
        }
    };

    ldgA(0); ldgB(0);
    stsA(0); stsB(0);
    __syncthreads();
#pragma unroll 1
    for (int kc = 0; kc < 8; kc++) {
        if (kc < 7) { ldgA(kc + 1); ldgB(kc + 1); }
        domma(kc & 1);
        if (kc < 7) {
            stsA((kc + 1) & 1); stsB((kc + 1) & 1);
            __syncthreads();
        }
    }

    if (winout) {
        // window layout: [(b*NWIN + win)*8 + head][c][tok]
#pragma unroll
        for (int mt = 0; mt < 4; mt++) {
#pragma unroll
            for (int nt = 0; nt < 4; nt++) {
                int m0  = mBase + wm * 64 + mt * 16 + (lane >> 2);
                int col = wn * 32 + nt * 8 + (lane & 3) * 2;
                int hw  = hw0 + col;
                int h   = hw >> 8;
                int wp  = hw & 255;
                int win = ((h >> 3) << 5) | (wp >> 3);
                int tok = ((h & 7) << 3) | (wp & 7);
                size_t wbase = ((size_t)(b * NWIN + win)) * 16384 + (size_t)tok;
#pragma unroll
                for (int rr = 0; rr < 2; rr++) {
                    int mm = m0 + rr * 8;
                    float* dst = Out + wbase + (size_t)(mm >> 5) * 2048
                                     + (size_t)(mm & 31) * 64;
                    *reinterpret_cast<float2*>(dst) =
                        make_float2(acc[mt][nt][rr * 2], acc[mt][nt][rr * 2 + 1]);
                }
            }
        }
    } else {
#pragma unroll
        for (int mt = 0; mt < 4; mt++) {
#pragma unroll
            for (int nt = 0; nt < 4; nt++) {
                int m   = mBase + wm * 64 + mt * 16 + (lane >> 2);
                int col = wn * 32 + nt * 8 + (lane & 3) * 2;
                float* r0 = Ob + (size_t)m * HW + col;
                *reinterpret_cast<float2*>(r0) = make_float2(acc[mt][nt][0], acc[mt][nt][1]);
                *reinterpret_cast<float2*>(r0 + (size_t)8 * HW) =
                    make_float2(acc[mt][nt][2], acc[mt][nt][3]);
            }
        }
    }
}

__global__ __launch_bounds__(256, 2) void qkv_kernel(const float* __restrict__ x)
{
    int mat   = blockIdx.y >> 1;
    int mhalf = blockIdx.y & 1;
    float* Out = (mat == 0) ? g_q : (mat == 1) ? g_k : g_v;
    const uint32_t* Wz = g_swzW + ((size_t)mat * 16 + mhalf * 8) * 16 * 128;
    gemm_tc(Wz, x, Out, mhalf * 128, blockIdx.x, 1);
}

__global__ __launch_bounds__(256, 2) void wo_kernel(float* __restrict__ out)
{
    int mhalf = blockIdx.y;
    const uint32_t* Wz = g_swzW + ((size_t)3 * 16 + mhalf * 8) * 16 * 128;
    gemm_tc(Wz, g_ao, out, mhalf * 128, blockIdx.x, 0);
}

// ---------------------------------------------------------------------------
// Tensor-core windowed attention (unchanged from R12 winner). Block = 64
// threads = 2 warps = one (window, head); q/k/v in WINDOW layout (coalesced).
// Smem 27 KB: Vt[2304]; KQ[4608] = Kt | Qw during S phase, reused as Pw.
// ---------------------------------------------------------------------------
__global__ __launch_bounds__(64) void attn_tc_kernel()
{
    __shared__ uint32_t Vt[32 * 72];     // 2304
    __shared__ uint32_t KQ[4608];        // Kt | Qw -> later Pw

    const int bidx = blockIdx.x;         // (b*NWIN + win)*8 + head
    const int head = bidx & 7;
    const int win  = bidx >> 3;
    const int b    = win >> 10;
    const int wh   = (win >> 5) & 31;
    const int ww   = win & 31;
    const int tid  = threadIdx.x;
    const int w    = tid >> 5;
    const int lane = tid & 31;

    uint32_t* Kt = KQ;
    uint32_t* Qw = KQ + 2304 + w * 1152;   // stride-36 rows
    uint32_t* Pw = KQ + w * 2176;          // stride-68 rows (valid after sync)

    const size_t src = (size_t)bidx * 2048;          // window-layout base
    const size_t obase = (size_t)b * CC * HW + (size_t)(head * HD) * HW
                       + (size_t)(wh * 8) * WW2 + (size_t)(ww * 8);

    // ---- load (coalesced: lanes = consecutive tokens) ----
    {
        const int j = tid;
        const float scale = 0.17677669529663687f;   // 32^-0.5
        const int qsw = ((lane >> 3) & 3) << 3;
#pragma unroll
        for (int c = 0; c < HD; c++) {
            size_t a = src + (size_t)c * 64 + j;
            Kt[c * 72 + j] = f2tf32(g_k[a]);
            Vt[c * 72 + j] = f2tf32(g_v[a]);
            Qw[lane * 36 + (c ^ qsw)] = f2tf32(g_q[a] * scale);
        }
    }
    __syncthreads();

    // ---- S = Q^T K ----
    float s[2][8][4];
#pragma unroll
    for (int mt = 0; mt < 2; mt++)
#pragma unroll
        for (int nt = 0; nt < 8; nt++)
#pragma unroll
            for (int e = 0; e < 4; e++) s[mt][nt][e] = 0.f;

#pragma unroll
    for (int kt = 0; kt < 4; kt++) {
        uint32_t a[2][4];
#pragma unroll
        for (int mt = 0; mt < 2; mt++)
#pragma unroll
            for (int sl = 0; sl < 4; sl++) {
                int ir = (lane >> 2) + 8 * (sl & 1) + 16 * mt;
                int c  = (lane & 3) + 4 * (sl >> 1) + 8 * kt;
                int ks = ((ir >> 3) & 3) << 3;
                a[mt][sl] = Qw[ir * 36 + (c ^ ks)];
            }
#pragma unroll
        for (int nt = 0; nt < 8; nt++) {
            int cb = 8 * kt + (lane & 3);
            int jj = 8 * nt + (lane >> 2);
            uint32_t b0 = Kt[cb * 72 + jj];
            uint32_t b1 = Kt[(cb + 4) * 72 + jj];
#pragma unroll
            for (int mt = 0; mt < 2; mt++)
                mma_tf32(s[mt][nt][0], s[mt][nt][1], s[mt][nt][2], s[mt][nt][3],
                         a[mt][0], a[mt][1], a[mt][2], a[mt][3], b0, b1);
        }
    }

    // ---- softmax (register-only, quad shuffles) ----
    float mx[2][2] = {{-1e30f, -1e30f}, {-1e30f, -1e30f}};
#pragma unroll
    for (int mt = 0; mt < 2; mt++)
#pragma unroll
        for (int nt = 0; nt < 8; nt++) {
            mx[mt][0] = fmaxf(mx[mt][0], fmaxf(s[mt][nt][0], s[mt][nt][1]));
            mx[mt][1] = fmaxf(mx[mt][1], fmaxf(s[mt][nt][2], s[mt][nt][3]));
        }
#pragma unroll
    for (int mt = 0; mt < 2; mt++)
#pragma unroll
        for (int hi = 0; hi < 2; hi++) {
            float v = mx[mt][hi];
            v = fmaxf(v, __shfl_xor_sync(0xffffffffu, v, 1));
            v = fmaxf(v, __shfl_xor_sync(0xffffffffu, v, 2));
            mx[mt][hi] = v;
        }
    float sum[2][2] = {{0.f, 0.f}, {0.f, 0.f}};
#pragma unroll
    for (int mt = 0; mt < 2; mt++)
#pragma unroll
        for (int nt = 0; nt < 8; nt++) {
#pragma unroll
            for (int e = 0; e < 4; e++) {
                float p = __expf(s[mt][nt][e] - mx[mt][e >> 1]);
                s[mt][nt][e] = p;
                sum[mt][e >> 1] += p;
            }
        }
    float inv[2][2];
#pragma unroll
    for (int mt = 0; mt < 2; mt++)
#pragma unroll
        for (int hi = 0; hi < 2; hi++) {
            float v = sum[mt][hi];
            v += __shfl_xor_sync(0xffffffffu, v, 1);
            v += __shfl_xor_sync(0xffffffffu, v, 2);
            inv[mt][hi] = 1.f / v;
        }

    // ---- all Kt/Qw reads done -> safe to overlay Pw ----
    __syncthreads();

    // ---- P -> smem (tf32, unnormalized) ----
#pragma unroll
    for (int mt = 0; mt < 2; mt++)
#pragma unroll
        for (int nt = 0; nt < 8; nt++) {
            int rlo = (lane >> 2) + 16 * mt;
            int col = 2 * (lane & 3) + 8 * nt;
            uint2 lo = make_uint2(f2tf32(s[mt][nt][0]), f2tf32(s[mt][nt][1]));
            uint2 hi = make_uint2(f2tf32(s[mt][nt][2]), f2tf32(s[mt][nt][3]));
            *reinterpret_cast<uint2*>(&Pw[rlo * 68 + col]) = lo;
            *reinterpret_cast<uint2*>(&Pw[(rlo + 8) * 68 + col]) = hi;
        }
    __syncwarp();

    // ---- O = P V^T ----
    float o[2][4][4];
#pragma unroll
    for (int mt = 0; mt < 2; mt++)
#pragma unroll
        for (int nt = 0; nt < 4; nt++)
#pragma unroll
            for (int e = 0; e < 4; e++) o[mt][nt][e] = 0.f;

#pragma unroll
    for (int kt = 0; kt < 8; kt++) {
        uint32_t a[2][4];
#pragma unroll
        for (int mt = 0; mt < 2; mt++)
#pragma unroll
            for (int sl = 0; sl < 4; sl++) {
                int ir = (lane >> 2) + 8 * (sl & 1) + 16 * mt;
                int jj = (lane & 3) + 4 * (sl >> 1) + 8 * kt;
                a[mt][sl] = Pw[ir * 68 + jj];
            }
#pragma unroll
        for (int nt = 0; nt < 4; nt++) {
            int cc = 8 * nt + (lane >> 2);
            int jb = 8 * kt + (lane & 3);
            uint32_t b0 = Vt[cc * 72 + jb];
            uint32_t b1 = Vt[cc * 72 + jb + 4];
#pragma unroll
            for (int mt = 0; mt < 2; mt++)
                mma_tf32(o[mt][nt][0], o[mt][nt][1], o[mt][nt][2], o[mt][nt][3],
                         a[mt][0], a[mt][1], a[mt][2], a[mt][3], b0, b1);
        }
    }

    // ---- epilogue: scale by 1/rowsum, scatter to g_ao [B][C][HW] ----
#pragma unroll
    for (int mt = 0; mt < 2; mt++)
#pragma unroll
        for (int nt = 0; nt < 4; nt++)
#pragma unroll
            for (int e = 0; e < 4; e++) {
                int rp  = (lane >> 2) + 8 * (e >> 1) + 16 * mt;
                int tok = w * 32 + rp;
                int cl  = 2 * (lane & 3) + (e & 1) + 8 * nt;
                g_ao[obase + (size_t)cl * HW + (size_t)(tok >> 3) * WW2 + (tok & 7)]
                    = o[mt][nt][e] * inv[mt][e >> 1];
            }
}

// ---------------------------------------------------------------------------
extern "C" void kernel_launch(void* const* d_in, const int* in_sizes, int n_in,
                              void* d_out, int out_size)
{
    const float* x  = (const float*)d_in[0];
    const float* Wq = (const float*)d_in[1];
    const float* Wk = (const float*)d_in[2];
    const float* Wv = (const float*)d_in[3];
    const float* Wo = (const float*)d_in[4];
    float* out = (float*)d_out;

    swz_kernel<<<128, 256>>>(Wq, Wk, Wv, Wo);
    qkv_kernel<<<dim3(NTILE, 6), 256>>>(x);
    attn_tc_kernel<<<BB * NWIN * HEADS, 64>>>();
    wo_kernel<<<dim3(NTILE, 2), 256>>>(out);
}

// round 14
// speedup vs baseline: 1.8267x; 1.0948x over previous
#include <cuda_runtime.h>
#include <cuda_fp16.h>
#include <cstdint>

#define BB    4
#define CC    256
#define HH    256
#define WW2   256
#define HW    65536          // HH*WW2
#define NPIX  262144         // BB*HW
#define NTILE 2048           // NPIX/128
#define HEADS 8
#define HD    32
#define NWIN  1024           // (HH/8)*(WW2/8)

// fp16 activations:
__device__ __half g_xh [BB * CC * HW];   // x converted to fp16, [B][C][HW]
// q, k, v fp16 in WINDOW layout: [(b*NWIN+win)*HEADS + head][c(32)][tok(64)]
__device__ __half g_qh [BB * CC * HW];
__device__ __half g_kh [BB * CC * HW];
__device__ __half g_vh [BB * CC * HW];
// attention output fp16 in [B][C][HW] (input for wo GEMM)
__device__ __half g_aoh[BB * CC * HW];

// Pre-swizzled weights as fp16 m16n8k16 A fragments.
// Layout: [mat(4)][mtile(16)][ktile(16)][lane(32)][reg(4)]  (u32 = half2)
__device__ uint32_t g_swzW[4 * 16 * 16 * 128];

__device__ __forceinline__ uint32_t f2tf32(float f) {
    uint32_t u;
    asm("cvt.rna.tf32.f32 %0, %1;" : "=r"(u) : "f"(f));
    return u;
}

__device__ __forceinline__ uint32_t pack_h2(float lo, float hi) {
    __half2 h = __floats2half2_rn(lo, hi);
    return *reinterpret_cast<uint32_t*>(&h);
}
__device__ __forceinline__ uint32_t h2u(__half2 h) {
    return *reinterpret_cast<uint32_t*>(&h);
}

// B smem intra-tile swizzle: write/read mirror, conflict-free both sides.
__device__ __forceinline__ int swzB(int l) {
    return (l * 2) ^ (((l >> 4) & 1) << 3);
}

__device__ __forceinline__ void mma_f16(float& c0, float& c1, float& c2, float& c3,
                                        uint32_t a0, uint32_t a1, uint32_t a2, uint32_t a3,
                                        uint32_t b0, uint32_t b1) {
    asm volatile(
        "mma.sync.aligned.m16n8k16.row.col.f32.f16.f16.f32 "
        "{%0,%1,%2,%3}, {%4,%5,%6,%7}, {%8,%9}, {%0,%1,%2,%3};\n"
        : "+f"(c0), "+f"(c1), "+f"(c2), "+f"(c3)
        : "r"(a0), "r"(a1), "r"(a2), "r"(a3), "r"(b0), "r"(b1));
}

__device__ __forceinline__ void mma_tf32(float& c0, float& c1, float& c2, float& c3,
                                         uint32_t a0, uint32_t a1, uint32_t a2, uint32_t a3,
                                         uint32_t b0, uint32_t b1) {
    asm volatile(
        "mma.sync.aligned.m16n8k8.row.col.f32.tf32.tf32.f32 "
        "{%0,%1,%2,%3}, {%4,%5,%6,%7}, {%8,%9}, {%0,%1,%2,%3};\n"
        : "+f"(c0), "+f"(c1), "+f"(c2), "+f"(c3)
        : "r"(a0), "r"(a1), "r"(a2), "r"(a3), "r"(b0), "r"(b1));
}

// ---------------------------------------------------------------------------
// x (fp32) -> g_xh (fp16), vectorized.
// ---------------------------------------------------------------------------
__global__ __launch_bounds__(256) void cvt_kernel(const float* __restrict__ x)
{
    size_t i = ((size_t)blockIdx.x * 256 + threadIdx.x) * 4;
    float4 v = *reinterpret_cast<const float4*>(x + i);
    uint2 o = make_uint2(pack_h2(v.x, v.y), pack_h2(v.z, v.w));
    *reinterpret_cast<uint2*>(&g_xh[i]) = o;
}

// ---------------------------------------------------------------------------
// One-shot weight pre-swizzle: W[m][k] -> fp16 m16n8k16 A-fragment order.
// ---------------------------------------------------------------------------
__global__ __launch_bounds__(256) void swz_kernel(const float* __restrict__ Wq,
                                                  const float* __restrict__ Wk,
                                                  const float* __restrict__ Wv,
                                                  const float* __restrict__ Wo)
{
    int idx = blockIdx.x * 256 + threadIdx.x;      // 32768 total
    int lane = idx & 31;
    int kt   = (idx >> 5) & 15;
    int mt   = (idx >> 9) & 15;
    int mat  = idx >> 13;
    const float* W = (mat == 0) ? Wq : (mat == 1) ? Wk : (mat == 2) ? Wv : Wo;

    uint32_t o[4];
#pragma unroll
    for (int s = 0; s < 4; s++) {
        int r = mt * 16 + (lane >> 2) + 8 * (s & 1);
        int c = kt * 16 + 2 * (lane & 3) + 8 * (s >> 1);
        o[s] = pack_h2(W[r * CC + c], W[r * CC + c + 1]);
    }
    *reinterpret_cast<uint4*>(&g_swzW[(size_t)idx * 4]) = make_uint4(o[0], o[1], o[2], o[3]);
}

// ---------------------------------------------------------------------------
// fp16 tensor-core GEMM over fp16 input X: Out[m, p] = sum_k W[m, k]*X[k, p]
// Block tile 128(m) x 128(p), K-chunk 32 (2 k16 subtiles), double-buffered.
// winout=1 -> half output scattered to window layout; else fp32 [B][C][HW].
// ---------------------------------------------------------------------------
__device__ __forceinline__ void gemm_tc(const uint32_t* __restrict__ Wz,
                                        const __half* __restrict__ X,
                                        __half* __restrict__ OutH,
                                        float* __restrict__ OutF,
                                        int mBase, int pTile, int winout)
{
    __shared__ alignas(16) uint32_t As[2][2112];   // 16 tiles (kt2*8+mt) x 132
    __shared__ alignas(16) uint32_t Bs[2][2112];   // 32 tiles (kt2*16+nt) x 66

    const int tid  = threadIdx.x;
    const int w    = tid >> 5;
    const int lane = tid & 31;
    const int wm   = w & 1;
    const int wn   = w >> 1;

    const int p0  = pTile * 128;
    const int b   = p0 >> 16;
    const int hw0 = p0 & (HW - 1);
    const __half* Xb = X + (size_t)b * CC * HW + hw0;

    float acc[4][4][4];
#pragma unroll
    for (int i = 0; i < 4; i++)
#pragma unroll
        for (int j = 0; j < 4; j++)
#pragma unroll
            for (int e = 0; e < 4; e++) acc[i][j][e] = 0.f;

    uint4   aR[2];
    __half2 bR[2][4];      // [kt2][row: 2t,2t+1,2t+8,2t+9], each = 2 pixels

    const int tq = tid >> 6;        // 0..3 : k-pair group
    const int p2 = tid & 63;        // pixel pair

    auto ldgA = [&](int kc) {       // kc in 0..7
#pragma unroll
        for (int u = 0; u < 2; u++) {
            int j = tid + u * 256;
            int t = j >> 5;                 // kt2*8 + mt
            int l = j & 31;
            int kt2 = t >> 3, mt = t & 7;
            aR[u] = *reinterpret_cast<const uint4*>(
                Wz + ((size_t)mt * 16 + (size_t)(kc * 2 + kt2)) * 128 + l * 4);
        }
    };
    auto stsA = [&](int buf) {
#pragma unroll
        for (int u = 0; u < 2; u++) {
            int j = tid + u * 256;
            int t = j >> 5;
            int l = j & 31;
            *reinterpret_cast<uint4*>(&As[buf][t * 132 + l * 4]) = aR[u];
        }
    };
    auto ldgB = [&](int kc) {
#pragma unroll
        for (int kt2 = 0; kt2 < 2; kt2++) {
            int kb = kc * 32 + kt2 * 16;
#pragma unroll
            for (int r = 0; r < 4; r++) {
                int krow = kb + 2 * tq + (r & 1) + 8 * (r >> 1);
                bR[kt2][r] = *reinterpret_cast<const __half2*>(
                    Xb + (size_t)krow * HW + p2 * 2);
            }
        }
    };
    auto stsB = [&](int buf) {
#pragma unroll
        for (int kt2 = 0; kt2 < 2; kt2++) {
#pragma unroll
            for (int e = 0; e < 2; e++) {
                int p = 2 * p2 + e;
                __half2 kp01 = e ? __highs2half2(bR[kt2][0], bR[kt2][1])
                                 : __lows2half2 (bR[kt2][0], bR[kt2][1]);
                __half2 kp23 = e ? __highs2half2(bR[kt2][2], bR[kt2][3])
                                 : __lows2half2 (bR[kt2][2], bR[kt2][3]);
                uint2 regs = make_uint2(h2u(kp01), h2u(kp23));
                int tile = kt2 * 16 + (p >> 3);
                int l    = (p & 7) * 4 + tq;
                *reinterpret_cast<uint2*>(&Bs[buf][tile * 66 + swzB(l)]) = regs;
            }
        }
    };
    const int swzlane = swzB(lane);
    auto domma = [&](int buf) {
#pragma unroll
        for (int kt2 = 0; kt2 < 2; kt2++) {
            uint4 a[4];
            uint2 bb[4];
#pragma unroll
            for (int mt = 0; mt < 4; mt++)
                a[mt] = *reinterpret_cast<const uint4*>(
                    &As[buf][(kt2 * 8 + wm * 4 + mt) * 132 + lane * 4]);
#pragma unroll
            for (int nt = 0; nt < 4; nt++)
                bb[nt] = *reinterpret_cast<const uint2*>(
                    &Bs[buf][(kt2 * 16 + wn * 4 + nt) * 66 + swzlane]);
#pragma unroll
            for (int mt = 0; mt < 4; mt++)
#pragma unroll
                for (int nt = 0; nt < 4; nt++)
                    mma_f16(acc[mt][nt][0], acc[mt][nt][1], acc[mt][nt][2], acc[mt][nt][3],
                            a[mt].x, a[mt].y, a[mt].z, a[mt].w, bb[nt].x, bb[nt].y);
        }
    };

    ldgA(0); ldgB(0);
    stsA(0); stsB(0);
    __syncthreads();
#pragma unroll 1
    for (int kc = 0; kc < 8; kc++) {
        if (kc < 7) { ldgA(kc + 1); ldgB(kc + 1); }
        domma(kc & 1);
        if (kc < 7) {
            stsA((kc + 1) & 1); stsB((kc + 1) & 1);
            __syncthreads();
        }
    }

    if (winout) {
        // half output, window layout: [(b*NWIN + win)*8 + head][c][tok]
#pragma unroll
        for (int mt = 0; mt < 4; mt++) {
#pragma unroll
            for (int nt = 0; nt < 4; nt++) {
                int m0  = mBase + wm * 64 + mt * 16 + (lane >> 2);
                int col = wn * 32 + nt * 8 + (lane & 3) * 2;
                int hw  = hw0 + col;
                int h   = hw >> 8;
                int wp  = hw & 255;
                int win = ((h >> 3) << 5) | (wp >> 3);
                int tok = ((h & 7) << 3) | (wp & 7);
                size_t wbase = ((size_t)(b * NWIN + win)) * 16384 + (size_t)tok;
#pragma unroll
                for (int rr = 0; rr < 2; rr++) {
                    int mm = m0 + rr * 8;
                    __half* dst = OutH + wbase + (size_t)(mm >> 5) * 2048
                                       + (size_t)(mm & 31) * 64;
                    *reinterpret_cast<uint32_t*>(dst) =
                        pack_h2(acc[mt][nt][rr * 2], acc[mt][nt][rr * 2 + 1]);
                }
            }
        }
    } else {
        float* Ob = OutF + (size_t)b * CC * HW + hw0;
#pragma unroll
        for (int mt = 0; mt < 4; mt++) {
#pragma unroll
            for (int nt = 0; nt < 4; nt++) {
                int m   = mBase + wm * 64 + mt * 16 + (lane >> 2);
                int col = wn * 32 + nt * 8 + (lane & 3) * 2;
                float* r0 = Ob + (size_t)m * HW + col;
                *reinterpret_cast<float2*>(r0) = make_float2(acc[mt][nt][0], acc[mt][nt][1]);
                *reinterpret_cast<float2*>(r0 + (size_t)8 * HW) =
                    make_float2(acc[mt][nt][2], acc[mt][nt][3]);
            }
        }
    }
}

// Grid (6, NTILE): blockIdx.x = pass (mat, mhalf) so same-ptile passes are
// adjacent -> B tile served from L2 after first pass.
__global__ __launch_bounds__(256, 2) void qkv_kernel()
{
    int mat   = blockIdx.x >> 1;
    int mhalf = blockIdx.x & 1;
    __half* Out = (mat == 0) ? g_qh : (mat == 1) ? g_kh : g_vh;
    const uint32_t* Wz = g_swzW + ((size_t)mat * 16 + mhalf * 8) * 16 * 128;
    gemm_tc(Wz, g_xh, Out, nullptr, mhalf * 128, blockIdx.y, 1);
}

__global__ __launch_bounds__(256, 2) void wo_kernel(float* __restrict__ out)
{
    int mhalf = blockIdx.x;
    const uint32_t* Wz = g_swzW + ((size_t)3 * 16 + mhalf * 8) * 16 * 128;
    gemm_tc(Wz, g_aoh, nullptr, out, mhalf * 128, blockIdx.y, 0);
}

// ---------------------------------------------------------------------------
// Tensor-core windowed attention (R12/13-proven compute). fp16 q/k/v in,
// fp16 g_aoh out. Smem 27 KB; Pw overlays Kt|Qw after sync.
// ---------------------------------------------------------------------------
__global__ __launch_bounds__(64) void attn_tc_kernel()
{
    __shared__ uint32_t Vt[32 * 72];     // 2304
    __shared__ uint32_t KQ[4608];        // Kt | Qw -> later Pw

    const int bidx = blockIdx.x;         // (b*NWIN + win)*8 + head
    const int head = bidx & 7;
    const int win  = bidx >> 3;
    const int b    = win >> 10;
    const int wh   = (win >> 5) & 31;
    const int ww   = win & 31;
    const int tid  = threadIdx.x;
    const int w    = tid >> 5;
    const int lane = tid & 31;

    uint32_t* Kt = KQ;
    uint32_t* Qw = KQ + 2304 + w * 1152;   // stride-36 rows
    uint32_t* Pw = KQ + w * 2176;          // stride-68 rows (valid after sync)

    const size_t src = (size_t)bidx * 2048;          // window-layout base
    const size_t obase = (size_t)b * CC * HW + (size_t)(head * HD) * HW
                       + (size_t)(wh * 8) * WW2 + (size_t)(ww * 8);

    // ---- load (coalesced halves: lanes = consecutive tokens) ----
    {
        const int j = tid;
        const float scale = 0.17677669529663687f;   // 32^-0.5
        const int qsw = ((lane >> 3) & 3) << 3;
#pragma unroll
        for (int c = 0; c < HD; c++) {
            size_t a = src + (size_t)c * 64 + j;
            Kt[c * 72 + j] = f2tf32(__half2float(g_kh[a]));
            Vt[c * 72 + j] = f2tf32(__half2float(g_vh[a]));
            Qw[lane * 36 + (c ^ qsw)] = f2tf32(__half2float(g_qh[a]) * scale);
        }
    }
    __syncthreads();

    // ---- S = Q^T K ----
    float s[2][8][4];
#pragma unroll
    for (int mt = 0; mt < 2; mt++)
#pragma unroll
        for (int nt = 0; nt < 8; nt++)
#pragma unroll
            for (int e = 0; e < 4; e++) s[mt][nt][e] = 0.f;

#pragma unroll
    for (int kt = 0; kt < 4; kt++) {
        uint32_t a[2][4];
#pragma unroll
        for (int mt = 0; mt < 2; mt++)
#pragma unroll
            for (int sl = 0; sl < 4; sl++) {
                int ir = (lane >> 2) + 8 * (sl & 1) + 16 * mt;
                int c  = (lane & 3) + 4 * (sl >> 1) + 8 * kt;
                int ks = ((ir >> 3) & 3) << 3;
                a[mt][sl] = Qw[ir * 36 + (c ^ ks)];
            }
#pragma unroll
        for (int nt = 0; nt < 8; nt++) {
            int cb = 8 * kt + (lane & 3);
            int jj = 8 * nt + (lane >> 2);
            uint32_t b0 = Kt[cb * 72 + jj];
            uint32_t b1 = Kt[(cb + 4) * 72 + jj];
#pragma unroll
            for (int mt = 0; mt < 2; mt++)
                mma_tf32(s[mt][nt][0], s[mt][nt][1], s[mt][nt][2], s[mt][nt][3],
                         a[mt][0], a[mt][1], a[mt][2], a[mt][3], b0, b1);
        }
    }

    // ---- softmax (register-only, quad shuffles) ----
    float mx[2][2] = {{-1e30f, -1e30f}, {-1e30f, -1e30f}};
#pragma unroll
    for (int mt = 0; mt < 2; mt++)
#pragma unroll
        for (int nt = 0; nt < 8; nt++) {
            mx[mt][0] = fmaxf(mx[mt][0], fmaxf(s[mt][nt][0], s[mt][nt][1]));
            mx[mt][1] = fmaxf(mx[mt][1], fmaxf(s[mt][nt][2], s[mt][nt][3]));
        }
#pragma unroll
    for (int mt = 0; mt < 2; mt++)
#pragma unroll
        for (int hi = 0; hi < 2; hi++) {
            float v = mx[mt][hi];
            v = fmaxf(v, __shfl_xor_sync(0xffffffffu, v, 1));
            v = fmaxf(v, __shfl_xor_sync(0xffffffffu, v, 2));
            mx[mt][hi] = v;
        }
    float sum[2][2] = {{0.f, 0.f}, {0.f, 0.f}};
#pragma unroll
    for (int mt = 0; mt < 2; mt++)
#pragma unroll
        for (int nt = 0; nt < 8; nt++) {
#pragma unroll
            for (int e = 0; e < 4; e++) {
                float p = __expf(s[mt][nt][e] - mx[mt][e >> 1]);
                s[mt][nt][e] = p;
                sum[mt][e >> 1] += p;
            }
        }
    float inv[2][2];
#pragma unroll
    for (int mt = 0; mt < 2; mt++)
#pragma unroll
        for (int hi = 0; hi < 2; hi++) {
            float v = sum[mt][hi];
            v += __shfl_xor_sync(0xffffffffu, v, 1);
            v += __shfl_xor_sync(0xffffffffu, v, 2);
            inv[mt][hi] = 1.f / v;
        }

    // ---- all Kt/Qw reads done -> safe to overlay Pw ----
    __syncthreads();

    // ---- P -> smem (tf32, unnormalized) ----
#pragma unroll
    for (int mt = 0; mt < 2; mt++)
#pragma unroll
        for (int nt = 0; nt < 8; nt++) {
            int rlo = (lane >> 2) + 16 * mt;
            int col = 2 * (lane & 3) + 8 * nt;
            uint2 lo = make_uint2(f2tf32(s[mt][nt][0]), f2tf32(s[mt][nt][1]));
            uint2 hi = make_uint2(f2tf32(s[mt][nt][2]), f2tf32(s[mt][nt][3]));
            *reinterpret_cast<uint2*>(&Pw[rlo * 68 + col]) = lo;
            *reinterpret_cast<uint2*>(&Pw[(rlo + 8) * 68 + col]) = hi;
        }
    __syncwarp();

    // ---- O = P V^T ----
    float o[2][4][4];
#pragma unroll
    for (int mt = 0; mt < 2; mt++)
#pragma unroll
        for (int nt = 0; nt < 4; nt++)
#pragma unroll
            for (int e = 0; e < 4; e++) o[mt][nt][e] = 0.f;

#pragma unroll
    for (int kt = 0; kt < 8; kt++) {
        uint32_t a[2][4];
#pragma unroll
        for (int mt = 0; mt < 2; mt++)
#pragma unroll
            for (int sl = 0; sl < 4; sl++) {
                int ir = (lane >> 2) + 8 * (sl & 1) + 16 * mt;
                int jj = (lane & 3) + 4 * (sl >> 1) + 8 * kt;
                a[mt][sl] = Pw[ir * 68 + jj];
            }
#pragma unroll
        for (int nt = 0; nt < 4; nt++) {
            int cc = 8 * nt + (lane >> 2);
            int jb = 8 * kt + (lane & 3);
            uint32_t b0 = Vt[cc * 72 + jb];
            uint32_t b1 = Vt[cc * 72 + jb + 4];
#pragma unroll
            for (int mt = 0; mt < 2; mt++)
                mma_tf32(o[mt][nt][0], o[mt][nt][1], o[mt][nt][2], o[mt][nt][3],
                         a[mt][0], a[mt][1], a[mt][2], a[mt][3], b0, b1);
        }
    }

    // ---- epilogue: scale by 1/rowsum, fp16 scatter to g_aoh [B][C][HW] ----
#pragma unroll
    for (int mt = 0; mt < 2; mt++)
#pragma unroll
        for (int nt = 0; nt < 4; nt++)
#pragma unroll
            for (int e = 0; e < 4; e++) {
                int rp  = (lane >> 2) + 8 * (e >> 1) + 16 * mt;
                int tok = w * 32 + rp;
                int cl  = 2 * (lane & 3) + (e & 1) + 8 * nt;
                g_aoh[obase + (size_t)cl * HW + (size_t)(tok >> 3) * WW2 + (tok & 7)]
                    = __float2half(o[mt][nt][e] * inv[mt][e >> 1]);
            }
}

// ---------------------------------------------------------------------------
extern "C" void kernel_launch(void* const* d_in, const int* in_sizes, int n_in,
                              void* d_out, int out_size)
{
    const float* x  = (const float*)d_in[0];
    const float* Wq = (const float*)d_in[1];
    const float* Wk = (const float*)d_in[2];
    const float* Wv = (const float*)d_in[3];
    const float* Wo = (const float*)d_in[4];
    float* out = (float*)d_out;

    swz_kernel<<<128, 256>>>(Wq, Wk, Wv, Wo);
    cvt_kernel<<<NPIX * CC / 1024, 256>>>(x);
    qkv_kernel<<<dim3(6, NTILE), 256>>>();
    attn_tc_kernel<<<BB * NWIN * HEADS, 64>>>();
    wo_kernel<<<dim3(2, NTILE), 256>>>(out);
}

// round 16
// speedup vs baseline: 2.1003x; 1.1497x over previous
#include <cuda_runtime.h>
#include <cuda_fp16.h>
#include <cstdint>

#define BB    4
#define CC    256
#define HH    256
#define WW2   256
#define HW    65536          // HH*WW2
#define NPIX  262144         // BB*HW
#define NTILE 2048           // NPIX/128
#define HEADS 8
#define HD    32
#define NWIN  1024           // (HH/8)*(WW2/8)

// fp16 activations:
__device__ __half g_xh [BB * CC * HW];   // x converted to fp16, [B][C][HW]
// q, k, v fp16 in WINDOW layout: [(b*NWIN+win)*HEADS + head][c(32)][tok(64)]
__device__ __half g_qh [BB * CC * HW];
__device__ __half g_kh [BB * CC * HW];
__device__ __half g_vh [BB * CC * HW];
// attention output fp16 in [B][C][HW] (input for wo GEMM)
__device__ __half g_aoh[BB * CC * HW];

// Pre-swizzled weights as fp16 m16n8k16 A fragments.
// Layout: [mat(4)][mtile(16)][ktile(16)][lane(32)][reg(4)]  (u32 = half2)
__device__ uint32_t g_swzW[4 * 16 * 16 * 128];

__device__ __forceinline__ uint32_t pack_h2(float lo, float hi) {
    __half2 h = __floats2half2_rn(lo, hi);
    return *reinterpret_cast<uint32_t*>(&h);
}
__device__ __forceinline__ uint32_t h2u(__half2 h) {
    return *reinterpret_cast<uint32_t*>(&h);
}

// B smem intra-tile swizzle (GEMM): write/read mirror, conflict-free.
__device__ __forceinline__ int swzB(int l) {
    return (l * 2) ^ (((l >> 4) & 1) << 3);
}

__device__ __forceinline__ void mma_f16(float& c0, float& c1, float& c2, float& c3,
                                        uint32_t a0, uint32_t a1, uint32_t a2, uint32_t a3,
                                        uint32_t b0, uint32_t b1) {
    asm volatile(
        "mma.sync.aligned.m16n8k16.row.col.f32.f16.f16.f32 "
        "{%0,%1,%2,%3}, {%4,%5,%6,%7}, {%8,%9}, {%0,%1,%2,%3};\n"
        : "+f"(c0), "+f"(c1), "+f"(c2), "+f"(c3)
        : "r"(a0), "r"(a1), "r"(a2), "r"(a3), "r"(b0), "r"(b1));
}

// ---------------------------------------------------------------------------
// x (fp32) -> g_xh (fp16), vectorized.
// ---------------------------------------------------------------------------
__global__ __launch_bounds__(256) void cvt_kernel(const float* __restrict__ x)
{
    size_t i = ((size_t)blockIdx.x * 256 + threadIdx.x) * 4;
    float4 v = *reinterpret_cast<const float4*>(x + i);
    uint2 o = make_uint2(pack_h2(v.x, v.y), pack_h2(v.z, v.w));
    *reinterpret_cast<uint2*>(&g_xh[i]) = o;
}

// ---------------------------------------------------------------------------
// One-shot weight pre-swizzle: W[m][k] -> fp16 m16n8k16 A-fragment order.
// Softmax scale (hd^-0.5) folded into Wq.
// ---------------------------------------------------------------------------
__global__ __launch_bounds__(256) void swz_kernel(const float* __restrict__ Wq,
                                                  const float* __restrict__ Wk,
                                                  const float* __restrict__ Wv,
                                                  const float* __restrict__ Wo)
{
    int idx = blockIdx.x * 256 + threadIdx.x;      // 32768 total
    int lane = idx & 31;
    int kt   = (idx >> 5) & 15;
    int mt   = (idx >> 9) & 15;
    int mat  = idx >> 13;
    const float* W = (mat == 0) ? Wq : (mat == 1) ? Wk : (mat == 2) ? Wv : Wo;
    const float sc = (mat == 0) ? 0.17677669529663687f : 1.0f;   // 32^-0.5 into Wq

    uint32_t o[4];
#pragma unroll
    for (int s = 0; s < 4; s++) {
        int r = mt * 16 + (lane >> 2) + 8 * (s & 1);
        int c = kt * 16 + 2 * (lane & 3) + 8 * (s >> 1);
        o[s] = pack_h2(W[r * CC + c] * sc, W[r * CC + c + 1] * sc);
    }
    *reinterpret_cast<uint4*>(&g_swzW[(size_t)idx * 4]) = make_uint4(o[0], o[1], o[2], o[3]);
}

// ---------------------------------------------------------------------------
// fp16 tensor-core GEMM over fp16 input X (unchanged from R14 winner).
// ---------------------------------------------------------------------------
__device__ __forceinline__ void gemm_tc(const uint32_t* __restrict__ Wz,
                                        const __half* __restrict__ X,
                                        __half* __restrict__ OutH,
                                        float* __restrict__ OutF,
                                        int mBase, int pTile, int winout)
{
    __shared__ alignas(16) uint32_t As[2][2112];   // 16 tiles (kt2*8+mt) x 132
    __shared__ alignas(16) uint32_t Bs[2][2112];   // 32 tiles (kt2*16+nt) x 66

    const int tid  = threadIdx.x;
    const int w    = tid >> 5;
    const int lane = tid & 31;
    const int wm   = w & 1;
    const int wn   = w >> 1;

    const int p0  = pTile * 128;
    const int b   = p0 >> 16;
    const int hw0 = p0 & (HW - 1);
    const __half* Xb = X + (size_t)b * CC * HW + hw0;

    float acc[4][4][4];
#pragma unroll
    for (int i = 0; i < 4; i++)
#pragma unroll
        for (int j = 0; j < 4; j++)
#pragma unroll
            for (int e = 0; e < 4; e++) acc[i][j][e] = 0.f;

    uint4   aR[2];
    __half2 bR[2][4];

    const int tq = tid >> 6;        // 0..3 : k-pair group
    const int p2 = tid & 63;        // pixel pair

    auto ldgA = [&](int kc) {
#pragma unroll
        for (int u = 0; u < 2; u++) {
            int j = tid + u * 256;
            int t = j >> 5;
            int l = j & 31;
            int kt2 = t >> 3, mt = t & 7;
            aR[u] = *reinterpret_cast<const uint4*>(
                Wz + ((size_t)mt * 16 + (size_t)(kc * 2 + kt2)) * 128 + l * 4);
        }
    };
    auto stsA = [&](int buf) {
#pragma unroll
        for (int u = 0; u < 2; u++) {
            int j = tid + u * 256;
            int t = j >> 5;
            int l = j & 31;
            *reinterpret_cast<uint4*>(&As[buf][t * 132 + l * 4]) = aR[u];
        }
    };
    auto ldgB = [&](int kc) {
#pragma unroll
        for (int kt2 = 0; kt2 < 2; kt2++) {
            int kb = kc * 32 + kt2 * 16;
#pragma unroll
            for (int r = 0; r < 4; r++) {
                int krow = kb + 2 * tq + (r & 1) + 8 * (r >> 1);
                bR[kt2][r] = *reinterpret_cast<const __half2*>(
                    Xb + (size_t)krow * HW + p2 * 2);
            }
        }
    };
    auto stsB = [&](int buf) {
#pragma unroll
        for (int kt2 = 0; kt2 < 2; kt2++) {
#pragma unroll
            for (int e = 0; e < 2; e++) {
                int p = 2 * p2 + e;
                __half2 kp01 = e ? __highs2half2(bR[kt2][0], bR[kt2][1])
                                 : __lows2half2 (bR[kt2][0], bR[kt2][1]);
                __half2 kp23 = e ? __highs2half2(bR[kt2][2], bR[kt2][3])
                                 : __lows2half2 (bR[kt2][2], bR[kt2][3]);
                uint2 regs = make_uint2(h2u(kp01), h2u(kp23));
                int tile = kt2 * 16 + (p >> 3);
                int l    = (p & 7) * 4 + tq;
                *reinterpret_cast<uint2*>(&Bs[buf][tile * 66 + swzB(l)]) = regs;
            }
        }
    };
    const int swzlane = swzB(lane);
    auto domma = [&](int buf) {
#pragma unroll
        for (int kt2 = 0; kt2 < 2; kt2++) {
            uint4 a[4];
            uint2 bb[4];
#pragma unroll
            for (int mt = 0; mt < 4; mt++)
                a[mt] = *reinterpret_cast<const uint4*>(
                    &As[buf][(kt2 * 8 + wm * 4 + mt) * 132 + lane * 4]);
#pragma unroll
            for (int nt = 0; nt < 4; nt++)
                bb[nt] = *reinterpret_cast<const uint2*>(
                    &Bs[buf][(kt2 * 16 + wn * 4 + nt) * 66 + swzlane]);
#pragma unroll
            for (int mt = 0; mt < 4; mt++)
#pragma unroll
                for (int nt = 0; nt < 4; nt++)
                    mma_f16(acc[mt][nt][0], acc[mt][nt][1], acc[mt][nt][2], acc[mt][nt][3],
                            a[mt].x, a[mt].y, a[mt].z, a[mt].w, bb[nt].x, bb[nt].y);
        }
    };

    ldgA(0); ldgB(0);
    stsA(0); stsB(0);
    __syncthreads();
#pragma unroll 1
    for (int kc = 0; kc < 8; kc++) {
        if (kc < 7) { ldgA(kc + 1); ldgB(kc + 1); }
        domma(kc & 1);
        if (kc < 7) {
            stsA((kc + 1) & 1); stsB((kc + 1) & 1);
            __syncthreads();
        }
    }

    if (winout) {
#pragma unroll
        for (int mt = 0; mt < 4; mt++) {
#pragma unroll
            for (int nt = 0; nt < 4; nt++) {
                int m0  = mBase + wm * 64 + mt * 16 + (lane >> 2);
                int col = wn * 32 + nt * 8 + (lane & 3) * 2;
                int hw  = hw0 + col;
                int h   = hw >> 8;
                int wp  = hw & 255;
                int win = ((h >> 3) << 5) | (wp >> 3);
                int tok = ((h & 7) << 3) | (wp & 7);
                size_t wbase = ((size_t)(b * NWIN + win)) * 16384 + (size_t)tok;
#pragma unroll
                for (int rr = 0; rr < 2; rr++) {
                    int mm = m0 + rr * 8;
                    __half* dst = OutH + wbase + (size_t)(mm >> 5) * 2048
                                       + (size_t)(mm & 31) * 64;
                    *reinterpret_cast<uint32_t*>(dst) =
                        pack_h2(acc[mt][nt][rr * 2], acc[mt][nt][rr * 2 + 1]);
                }
            }
        }
    } else {
        float* Ob = OutF + (size_t)b * CC * HW + hw0;
#pragma unroll
        for (int mt = 0; mt < 4; mt++) {
#pragma unroll
            for (int nt = 0; nt < 4; nt++) {
                int m   = mBase + wm * 64 + mt * 16 + (lane >> 2);
                int col = wn * 32 + nt * 8 + (lane & 3) * 2;
                float* r0 = Ob + (size_t)m * HW + col;
                *reinterpret_cast<float2*>(r0) = make_float2(acc[mt][nt][0], acc[mt][nt][1]);
                *reinterpret_cast<float2*>(r0 + (size_t)8 * HW) =
                    make_float2(acc[mt][nt][2], acc[mt][nt][3]);
            }
        }
    }
}

__global__ __launch_bounds__(256, 2) void qkv_kernel()
{
    int mat   = blockIdx.x >> 1;
    int mhalf = blockIdx.x & 1;
    __half* Out = (mat == 0) ? g_qh : (mat == 1) ? g_kh : g_vh;
    const uint32_t* Wz = g_swzW + ((size_t)mat * 16 + mhalf * 8) * 16 * 128;
    gemm_tc(Wz, g_xh, Out, nullptr, mhalf * 128, blockIdx.y, 1);
}

__global__ __launch_bounds__(256, 2) void wo_kernel(float* __restrict__ out)
{
    int mhalf = blockIdx.x;
    const uint32_t* Wz = g_swzW + ((size_t)3 * 16 + mhalf * 8) * 16 * 128;
    gemm_tc(Wz, g_aoh, nullptr, out, mhalf * 128, blockIdx.y, 0);
}

// ---------------------------------------------------------------------------
// fp16 m16n8k16 windowed attention, register-resident P.
// Block = 64 threads = 2 warps = one (window, head). Warp w owns rows 32w..+31.
// Smem 14 KB:
//   Qt/Kt: [c2(16)][tok/row(64)] stride 72, u32 = half2(ch 2c2, 2c2+1)
//   Vt:    [j2(32)][c ^ (j2>>2)] stride 40, u32 = half2(key 2j2, 2j2+1)
// S C-fragments ARE the P A-fragments (fp16 layout identity) -> no P smem.
// ---------------------------------------------------------------------------
__global__ __launch_bounds__(64) void attn_tc_kernel()
{
    __shared__ uint32_t Qt[16 * 72];
    __shared__ uint32_t Kt[16 * 72];
    __shared__ uint32_t Vt[32 * 40];

    const int bidx = blockIdx.x;         // (b*NWIN + win)*8 + head
    const int head = bidx & 7;
    const int win  = bidx >> 3;
    const int b    = win >> 10;
    const int wh   = (win >> 5) & 31;
    const int ww   = win & 31;
    const int tid  = threadIdx.x;
    const int w    = tid >> 5;
    const int lane = tid & 31;
    const int g    = lane >> 2;
    const int t    = lane & 3;

    const size_t src = (size_t)bidx * 2048;          // window-layout base
    const size_t obase = (size_t)b * CC * HW + (size_t)(head * HD) * HW
                       + (size_t)(wh * 8) * WW2 + (size_t)(ww * 8);

    // ---- load into fragment-friendly smem ----
    {
        const int j = tid;
        const __half* qp = g_qh + src;
        const __half* kp = g_kh + src;
#pragma unroll
        for (int c2 = 0; c2 < 16; c2++) {
            Qt[c2 * 72 + j] = h2u(__halves2half2(qp[2 * c2 * 64 + j],
                                                 qp[(2 * c2 + 1) * 64 + j]));
            Kt[c2 * 72 + j] = h2u(__halves2half2(kp[2 * c2 * 64 + j],
                                                 kp[(2 * c2 + 1) * 64 + j]));
        }
        // V: thread handles pair p, channel half ch; direct half2 loads.
        const int p  = tid & 31;
        const int ch = (tid >> 5) * 16;
        const uint32_t* vp = reinterpret_cast<const uint32_t*>(g_vh + src);
#pragma unroll
        for (int ci = 0; ci < 16; ci++) {
            int c = ch + ci;
            Vt[p * 40 + (c ^ (p >> 2))] = vp[c * 32 + p];
        }
    }
    __syncthreads();

    // ---- S = Q^T K  (m32 x n64 x k32, 2 k16 steps) ----
    float s[2][8][4];
#pragma unroll
    for (int mt = 0; mt < 2; mt++)
#pragma unroll
        for (int nt = 0; nt < 8; nt++)
#pragma unroll
            for (int e = 0; e < 4; e++) s[mt][nt][e] = 0.f;

#pragma unroll
    for (int kt = 0; kt < 2; kt++) {
        const int c2 = 8 * kt + t;
        uint32_t a[2][4];
#pragma unroll
        for (int mt = 0; mt < 2; mt++) {
            int row = 32 * w + 16 * mt + g;
            a[mt][0] = Qt[c2 * 72 + row];
            a[mt][1] = Qt[c2 * 72 + row + 8];
            a[mt][2] = Qt[(c2 + 4) * 72 + row];
            a[mt][3] = Qt[(c2 + 4) * 72 + row + 8];
        }
#pragma unroll
        for (int nt = 0; nt < 8; nt++) {
            int j = 8 * nt + g;
            uint32_t b0 = Kt[c2 * 72 + j];
            uint32_t b1 = Kt[(c2 + 4) * 72 + j];
#pragma unroll
            for (int mt = 0; mt < 2; mt++)
                mma_f16(s[mt][nt][0], s[mt][nt][1], s[mt][nt][2], s[mt][nt][3],
                        a[mt][0], a[mt][1], a[mt][2], a[mt][3], b0, b1);
        }
    }

    // ---- softmax (register-only, quad shuffles) ----
    float mx[2][2] = {{-1e30f, -1e30f}, {-1e30f, -1e30f}};
#pragma unroll
    for (int mt = 0; mt < 2; mt++)
#pragma unroll
        for (int nt = 0; nt < 8; nt++) {
            mx[mt][0] = fmaxf(mx[mt][0], fmaxf(s[mt][nt][0], s[mt][nt][1]));
            mx[mt][1] = fmaxf(mx[mt][1], fmaxf(s[mt][nt][2], s[mt][nt][3]));
        }
#pragma unroll
    for (int mt = 0; mt < 2; mt++)
#pragma unroll
        for (int hi = 0; hi < 2; hi++) {
            float v = mx[mt][hi];
            v = fmaxf(v, __shfl_xor_sync(0xffffffffu, v, 1));
            v = fmaxf(v, __shfl_xor_sync(0xffffffffu, v, 2));
            mx[mt][hi] = v;
        }
    float sum[2][2] = {{0.f, 0.f}, {0.f, 0.f}};
#pragma unroll
    for (int mt = 0; mt < 2; mt++)
#pragma unroll
        for (int nt = 0; nt < 8; nt++) {
#pragma unroll
            for (int e = 0; e < 4; e++) {
                float p = __expf(s[mt][nt][e] - mx[mt][e >> 1]);
                s[mt][nt][e] = p;
                sum[mt][e >> 1] += p;
            }
        }
    float inv[2][2];
#pragma unroll
    for (int mt = 0; mt < 2; mt++)
#pragma unroll
        for (int hi = 0; hi < 2; hi++) {
            float v = sum[mt][hi];
            v += __shfl_xor_sync(0xffffffffu, v, 1);
            v += __shfl_xor_sync(0xffffffffu, v, 2);
            inv[mt][hi] = 1.f / v;
        }

    // ---- O = P V^T (m32 x n32 x k64, 4 k16 steps); P packed from s regs ----
    float o[2][4][4];
#pragma unroll
    for (int mt = 0; mt < 2; mt++)
#pragma unroll
        for (int nt = 0; nt < 4; nt++)
#pragma unroll
            for (int e = 0; e < 4; e++) o[mt][nt][e] = 0.f;

#pragma unroll
    for (int kt = 0; kt < 4; kt++) {
        uint32_t a[2][4];
#pragma unroll
        for (int mt = 0; mt < 2; mt++) {
            a[mt][0] = pack_h2(s[mt][2 * kt][0] * inv[mt][0], s[mt][2 * kt][1] * inv[mt][0]);
            a[mt][1] = pack_h2(s[mt][2 * kt][2] * inv[mt][1], s[mt][2 * kt][3] * inv[mt][1]);
            a[mt][2] = pack_h2(s[mt][2 * kt + 1][0] * inv[mt][0], s[mt][2 * kt + 1][1] * inv[mt][0]);
            a[mt][3] = pack_h2(s[mt][2 * kt + 1][2] * inv[mt][1], s[mt][2 * kt + 1][3] * inv[mt][1]);
        }
        const int j2a = 8 * kt + t;
        const int j2b = j2a + 4;
#pragma unroll
        for (int nt = 0; nt < 4; nt++) {
            int c = 8 * nt + g;
            uint32_t b0 = Vt[j2a * 40 + (c ^ (j2a >> 2))];
            uint32_t b1 = Vt[j2b * 40 + (c ^ (j2b >> 2))];
#pragma unroll
            for (int mt = 0; mt < 2; mt++)
                mma_f16(o[mt][nt][0], o[mt][nt][1], o[mt][nt][2], o[mt][nt][3],
                        a[mt][0], a[mt][1], a[mt][2], a[mt][3], b0, b1);
        }
    }

    // ---- epilogue: fp16 scatter to g_aoh [B][C][HW] (already normalized) ----
#pragma unroll
    for (int mt = 0; mt < 2; mt++)
#pragma unroll
        for (int nt = 0; nt < 4; nt++)
#pragma unroll
            for (int e = 0; e < 4; e++) {
                int rp  = g + 8 * (e >> 1) + 16 * mt;
                int tok = w * 32 + rp;
                int cl  = 2 * t + (e & 1) + 8 * nt;
                g_aoh[obase + (size_t)cl * HW + (size_t)(tok >> 3) * WW2 + (tok & 7)]
                    = __float2half(o[mt][nt][e]);
            }
}

// ---------------------------------------------------------------------------
extern "C" void kernel_launch(void* const* d_in, const int* in_sizes, int n_in,
                              void* d_out, int out_size)
{
    const float* x  = (const float*)d_in[0];
    const float* Wq = (const float*)d_in[1];
    const float* Wk = (const float*)d_in[2];
    const float* Wv = (const float*)d_in[3];
    const float* Wo = (const float*)d_in[4];
    float* out = (float*)d_out;

    swz_kernel<<<128, 256>>>(Wq, Wk, Wv, Wo);
    cvt_kernel<<<NPIX * CC / 1024, 256>>>(x);
    qkv_kernel<<<dim3(6, NTILE), 256>>>();
    attn_tc_kernel<<<BB * NWIN * HEADS, 64>>>();
    wo_kernel<<<dim3(2, NTILE), 256>>>(out);
}

// round 17
// speedup vs baseline: 2.2863x; 1.0886x over previous
#include <cuda_runtime.h>
#include <cuda_fp16.h>
#include <cstdint>

#define BB    4
#define CC    256
#define HH    256
#define WW2   256
#define HW    65536          // HH*WW2
#define NPIX  262144         // BB*HW
#define NTILE 2048           // NPIX/128
#define HEADS 8
#define HD    32
#define NWIN  1024           // (HH/8)*(WW2/8)

// q, k, v fp16 in WINDOW layout: [(b*NWIN+win)*HEADS + head][c(32)][tok(64)]
__device__ __half g_qh [BB * CC * HW];
__device__ __half g_kh [BB * CC * HW];
__device__ __half g_vh [BB * CC * HW];
// attention output fp16, ALSO window layout (same indexing as q/k/v)
__device__ __half g_aow[BB * CC * HW];

// Pre-swizzled weights as fp16 m16n8k16 A fragments.
// Layout: [mat(4)][mtile(16)][ktile(16)][lane(32)][reg(4)]  (u32 = half2)
__device__ uint32_t g_swzW[4 * 16 * 16 * 128];

__device__ __forceinline__ uint32_t pack_h2(float lo, float hi) {
    __half2 h = __floats2half2_rn(lo, hi);
    return *reinterpret_cast<uint32_t*>(&h);
}
__device__ __forceinline__ uint32_t h2u(__half2 h) {
    return *reinterpret_cast<uint32_t*>(&h);
}

// B smem intra-tile swizzle (GEMM): write/read mirror, conflict-free.
__device__ __forceinline__ int swzB(int l) {
    return (l * 2) ^ (((l >> 4) & 1) << 3);
}

__device__ __forceinline__ void mma_f16(float& c0, float& c1, float& c2, float& c3,
                                        uint32_t a0, uint32_t a1, uint32_t a2, uint32_t a3,
                                        uint32_t b0, uint32_t b1) {
    asm volatile(
        "mma.sync.aligned.m16n8k16.row.col.f32.f16.f16.f32 "
        "{%0,%1,%2,%3}, {%4,%5,%6,%7}, {%8,%9}, {%0,%1,%2,%3};\n"
        : "+f"(c0), "+f"(c1), "+f"(c2), "+f"(c3)
        : "r"(a0), "r"(a1), "r"(a2), "r"(a3), "r"(b0), "r"(b1));
}

// ---------------------------------------------------------------------------
// One-shot weight pre-swizzle: W[m][k] -> fp16 m16n8k16 A-fragment order.
// Softmax scale (hd^-0.5) folded into Wq.
// ---------------------------------------------------------------------------
__global__ __launch_bounds__(256) void swz_kernel(const float* __restrict__ Wq,
                                                  const float* __restrict__ Wk,
                                                  const float* __restrict__ Wv,
                                                  const float* __restrict__ Wo)
{
    int idx = blockIdx.x * 256 + threadIdx.x;      // 32768 total
    int lane = idx & 31;
    int kt   = (idx >> 5) & 15;
    int mt   = (idx >> 9) & 15;
    int mat  = idx >> 13;
    const float* W = (mat == 0) ? Wq : (mat == 1) ? Wk : (mat == 2) ? Wv : Wo;
    const float sc = (mat == 0) ? 0.17677669529663687f : 1.0f;   // 32^-0.5 into Wq

    uint32_t o[4];
#pragma unroll
    for (int s = 0; s < 4; s++) {
        int r = mt * 16 + (lane >> 2) + 8 * (s & 1);
        int c = kt * 16 + 2 * (lane & 3) + 8 * (s >> 1);
        o[s] = pack_h2(W[r * CC + c] * sc, W[r * CC + c + 1] * sc);
    }
    *reinterpret_cast<uint4*>(&g_swzW[(size_t)idx * 4]) = make_uint4(o[0], o[1], o[2], o[3]);
}

// ---------------------------------------------------------------------------
// fp16 tensor-core GEMM. mode 0 (qkv): B = fp32 x in [B][C][HW], half output
// scattered to window layout. mode 1 (wo): B = fp16 g_aow in WINDOW layout
// (columns are window-ordered pixels), fp32 output scattered back to [B][C][HW].
// Block tile 128(m) x 128(p), K-chunk 32 (2 k16 subtiles), double-buffered.
// ---------------------------------------------------------------------------
__device__ __forceinline__ void gemm_tc(const uint32_t* __restrict__ Wz,
                                        const float* __restrict__ Xf,
                                        __half* __restrict__ OutH,
                                        float* __restrict__ OutF,
                                        int mBase, int pTile, int mode)
{
    __shared__ alignas(16) uint32_t As[2][2112];   // 16 tiles (kt2*8+mt) x 132
    __shared__ alignas(16) uint32_t Bs[2][2112];   // 32 tiles (kt2*16+nt) x 66

    const int tid  = threadIdx.x;
    const int w    = tid >> 5;
    const int lane = tid & 31;
    const int wm   = w & 1;
    const int wn   = w >> 1;

    const int p0  = pTile * 128;
    const int b   = p0 >> 16;
    const int hw0 = p0 & (HW - 1);
    const float* Xb = Xf ? (Xf + (size_t)b * CC * HW + hw0) : nullptr;
    const uint32_t* Vw = reinterpret_cast<const uint32_t*>(g_aow);

    float acc[4][4][4];
#pragma unroll
    for (int i = 0; i < 4; i++)
#pragma unroll
        for (int j = 0; j < 4; j++)
#pragma unroll
            for (int e = 0; e < 4; e++) acc[i][j][e] = 0.f;

    uint4   aR[2];
    float2  bRf[2][4];     // mode 0
    __half2 bRh[2][4];     // mode 1

    const int tq = tid >> 6;        // 0..3 : k-pair group
    const int p2 = tid & 63;        // pixel pair

    auto ldgA = [&](int kc) {
#pragma unroll
        for (int u = 0; u < 2; u++) {
            int j = tid + u * 256;
            int t = j >> 5;
            int l = j & 31;
            int kt2 = t >> 3, mt = t & 7;
            aR[u] = *reinterpret_cast<const uint4*>(
                Wz + ((size_t)mt * 16 + (size_t)(kc * 2 + kt2)) * 128 + l * 4);
        }
    };
    auto stsA = [&](int buf) {
#pragma unroll
        for (int u = 0; u < 2; u++) {
            int j = tid + u * 256;
            int t = j >> 5;
            int l = j & 31;
            *reinterpret_cast<uint4*>(&As[buf][t * 132 + l * 4]) = aR[u];
        }
    };
    auto ldgB = [&](int kc) {
#pragma unroll
        for (int kt2 = 0; kt2 < 2; kt2++) {
            int kb = kc * 32 + kt2 * 16;
#pragma unroll
            for (int r = 0; r < 4; r++) {
                int krow = kb + 2 * tq + (r & 1) + 8 * (r >> 1);
                if (mode == 0) {
                    bRf[kt2][r] = *reinterpret_cast<const float2*>(
                        Xb + (size_t)krow * HW + p2 * 2);
                } else {
                    // window layout: win = pTile*2 + (p2>>5), head = krow>>5
                    size_t idx = (((size_t)(pTile * 2 + (p2 >> 5)) * 8 + (krow >> 5)) * 1024)
                               + (size_t)(krow & 31) * 32 + (p2 & 31);
                    bRh[kt2][r] = *reinterpret_cast<const __half2*>(&Vw[idx]);
                }
            }
        }
    };
    auto stsB = [&](int buf) {
#pragma unroll
        for (int kt2 = 0; kt2 < 2; kt2++) {
#pragma unroll
            for (int e = 0; e < 2; e++) {
                int p = 2 * p2 + e;
                uint2 regs;
                if (mode == 0) {
                    float v0 = e ? bRf[kt2][0].y : bRf[kt2][0].x;
                    float v1 = e ? bRf[kt2][1].y : bRf[kt2][1].x;
                    float v2 = e ? bRf[kt2][2].y : bRf[kt2][2].x;
                    float v3 = e ? bRf[kt2][3].y : bRf[kt2][3].x;
                    regs = make_uint2(pack_h2(v0, v1), pack_h2(v2, v3));
                } else {
                    __half2 kp01 = e ? __highs2half2(bRh[kt2][0], bRh[kt2][1])
                                     : __lows2half2 (bRh[kt2][0], bRh[kt2][1]);
                    __half2 kp23 = e ? __highs2half2(bRh[kt2][2], bRh[kt2][3])
                                     : __lows2half2 (bRh[kt2][2], bRh[kt2][3]);
                    regs = make_uint2(h2u(kp01), h2u(kp23));
                }
                int tile = kt2 * 16 + (p >> 3);
                int l    = (p & 7) * 4 + tq;
                *reinterpret_cast<uint2*>(&Bs[buf][tile * 66 + swzB(l)]) = regs;
            }
        }
    };
    const int swzlane = swzB(lane);
    auto domma = [&](int buf) {
#pragma unroll
        for (int kt2 = 0; kt2 < 2; kt2++) {
            uint4 a[4];
            uint2 bb[4];
#pragma unroll
            for (int mt = 0; mt < 4; mt++)
                a[mt] = *reinterpret_cast<const uint4*>(
                    &As[buf][(kt2 * 8 + wm * 4 + mt) * 132 + lane * 4]);
#pragma unroll
            for (int nt = 0; nt < 4; nt++)
                bb[nt] = *reinterpret_cast<const uint2*>(
                    &Bs[buf][(kt2 * 16 + wn * 4 + nt) * 66 + swzlane]);
#pragma unroll
            for (int mt = 0; mt < 4; mt++)
#pragma unroll
                for (int nt = 0; nt < 4; nt++)
                    mma_f16(acc[mt][nt][0], acc[mt][nt][1], acc[mt][nt][2], acc[mt][nt][3],
                            a[mt].x, a[mt].y, a[mt].z, a[mt].w, bb[nt].x, bb[nt].y);
        }
    };

    ldgA(0); ldgB(0);
    stsA(0); stsB(0);
    __syncthreads();
#pragma unroll 1
    for (int kc = 0; kc < 8; kc++) {
        if (kc < 7) { ldgA(kc + 1); ldgB(kc + 1); }
        domma(kc & 1);
        if (kc < 7) {
            stsA((kc + 1) & 1); stsB((kc + 1) & 1);
            __syncthreads();
        }
    }

    if (mode == 0) {
        // half output, window layout: [(b*NWIN + win)*8 + head][c][tok]
#pragma unroll
        for (int mt = 0; mt < 4; mt++) {
#pragma unroll
            for (int nt = 0; nt < 4; nt++) {
                int m0  = mBase + wm * 64 + mt * 16 + (lane >> 2);
                int col = wn * 32 + nt * 8 + (lane & 3) * 2;
                int hw  = hw0 + col;
                int h   = hw >> 8;
                int wp  = hw & 255;
                int win = ((h >> 3) << 5) | (wp >> 3);
                int tok = ((h & 7) << 3) | (wp & 7);
                size_t wbase = ((size_t)(b * NWIN + win)) * 16384 + (size_t)tok;
#pragma unroll
                for (int rr = 0; rr < 2; rr++) {
                    int mm = m0 + rr * 8;
                    __half* dst = OutH + wbase + (size_t)(mm >> 5) * 2048
                                       + (size_t)(mm & 31) * 64;
                    *reinterpret_cast<uint32_t*>(dst) =
                        pack_h2(acc[mt][nt][rr * 2], acc[mt][nt][rr * 2 + 1]);
                }
            }
        }
    } else {
        // fp32 output: columns are WINDOW-ordered pixels -> map back to hw
#pragma unroll
        for (int mt = 0; mt < 4; mt++) {
#pragma unroll
            for (int nt = 0; nt < 4; nt++) {
                int m   = mBase + wm * 64 + mt * 16 + (lane >> 2);
                int col = wn * 32 + nt * 8 + (lane & 3) * 2;
                int P   = p0 + col;                       // window-ordered global pixel
                int bb2 = P >> 16;
                int wl  = (P >> 6) & (NWIN - 1);
                int tok = P & 63;
                int hw  = (((wl >> 5) * 8 + (tok >> 3)) << 8) | ((wl & 31) * 8 + (tok & 7));
                float* r0 = OutF + (size_t)bb2 * CC * HW + (size_t)m * HW + hw;
                *reinterpret_cast<float2*>(r0) = make_float2(acc[mt][nt][0], acc[mt][nt][1]);
                *reinterpret_cast<float2*>(r0 + (size_t)8 * HW) =
                    make_float2(acc[mt][nt][2], acc[mt][nt][3]);
            }
        }
    }
}

__global__ __launch_bounds__(256, 2) void qkv_kernel(const float* __restrict__ x)
{
    int mat   = blockIdx.x >> 1;
    int mhalf = blockIdx.x & 1;
    __half* Out = (mat == 0) ? g_qh : (mat == 1) ? g_kh : g_vh;
    const uint32_t* Wz = g_swzW + ((size_t)mat * 16 + mhalf * 8) * 16 * 128;
    gemm_tc(Wz, x, Out, nullptr, mhalf * 128, blockIdx.y, 0);
}

__global__ __launch_bounds__(256, 2) void wo_kernel(float* __restrict__ out)
{
    int mhalf = blockIdx.x;
    const uint32_t* Wz = g_swzW + ((size_t)3 * 16 + mhalf * 8) * 16 * 128;
    gemm_tc(Wz, nullptr, nullptr, out, mhalf * 128, blockIdx.y, 1);
}

// ---------------------------------------------------------------------------
// fp16 m16n8k16 windowed attention, register-resident P (R16 winner).
// Output now goes to g_aow in the SAME window layout as the inputs:
// dst index = src + c*64 + tok  (full-sector coalesced, trivial addressing).
// ---------------------------------------------------------------------------
__global__ __launch_bounds__(64) void attn_tc_kernel()
{
    __shared__ uint32_t Qt[16 * 72];
    __shared__ uint32_t Kt[16 * 72];
    __shared__ uint32_t Vt[32 * 40];

    const int bidx = blockIdx.x;         // (b*NWIN + win)*8 + head
    const int tid  = threadIdx.x;
    const int w    = tid >> 5;
    const int lane = tid & 31;
    const int g    = lane >> 2;
    const int t    = lane & 3;

    const size_t src = (size_t)bidx * 2048;          // window-layout base

    // ---- load into fragment-friendly smem ----
    {
        const int j = tid;
        const __half* qp = g_qh + src;
        const __half* kp = g_kh + src;
#pragma unroll
        for (int c2 = 0; c2 < 16; c2++) {
            Qt[c2 * 72 + j] = h2u(__halves2half2(qp[2 * c2 * 64 + j],
                                                 qp[(2 * c2 + 1) * 64 + j]));
            Kt[c2 * 72 + j] = h2u(__halves2half2(kp[2 * c2 * 64 + j],
                                                 kp[(2 * c2 + 1) * 64 + j]));
        }
        const int p  = tid & 31;
        const int ch = (tid >> 5) * 16;
        const uint32_t* vp = reinterpret_cast<const uint32_t*>(g_vh + src);
#pragma unroll
        for (int ci = 0; ci < 16; ci++) {
            int c = ch + ci;
            Vt[p * 40 + (c ^ (p >> 2))] = vp[c * 32 + p];
        }
    }
    __syncthreads();

    // ---- S = Q^T K  (m32 x n64 x k32, 2 k16 steps) ----
    float s[2][8][4];
#pragma unroll
    for (int mt = 0; mt < 2; mt++)
#pragma unroll
        for (int nt = 0; nt < 8; nt++)
#pragma unroll
            for (int e = 0; e < 4; e++) s[mt][nt][e] = 0.f;

#pragma unroll
    for (int kt = 0; kt < 2; kt++) {
        const int c2 = 8 * kt + t;
        uint32_t a[2][4];
#pragma unroll
        for (int mt = 0; mt < 2; mt++) {
            int row = 32 * w + 16 * mt + g;
            a[mt][0] = Qt[c2 * 72 + row];
            a[mt][1] = Qt[c2 * 72 + row + 8];
            a[mt][2] = Qt[(c2 + 4) * 72 + row];
            a[mt][3] = Qt[(c2 + 4) * 72 + row + 8];
        }
#pragma unroll
        for (int nt = 0; nt < 8; nt++) {
            int j = 8 * nt + g;
            uint32_t b0 = Kt[c2 * 72 + j];
            uint32_t b1 = Kt[(c2 + 4) * 72 + j];
#pragma unroll
            for (int mt = 0; mt < 2; mt++)
                mma_f16(s[mt][nt][0], s[mt][nt][1], s[mt][nt][2], s[mt][nt][3],
                        a[mt][0], a[mt][1], a[mt][2], a[mt][3], b0, b1);
        }
    }

    // ---- softmax (register-only, quad shuffles) ----
    float mx[2][2] = {{-1e30f, -1e30f}, {-1e30f, -1e30f}};
#pragma unroll
    for (int mt = 0; mt < 2; mt++)
#pragma unroll
        for (int nt = 0; nt < 8; nt++) {
            mx[mt][0] = fmaxf(mx[mt][0], fmaxf(s[mt][nt][0], s[mt][nt][1]));
            mx[mt][1] = fmaxf(mx[mt][1], fmaxf(s[mt][nt][2], s[mt][nt][3]));
        }
#pragma unroll
    for (int mt = 0; mt < 2; mt++)
#pragma unroll
        for (int hi = 0; hi < 2; hi++) {
            float v = mx[mt][hi];
            v = fmaxf(v, __shfl_xor_sync(0xffffffffu, v, 1));
            v = fmaxf(v, __shfl_xor_sync(0xffffffffu, v, 2));
            mx[mt][hi] = v;
        }
    float sum[2][2] = {{0.f, 0.f}, {0.f, 0.f}};
#pragma unroll
    for (int mt = 0; mt < 2; mt++)
#pragma unroll
        for (int nt = 0; nt < 8; nt++) {
#pragma unroll
            for (int e = 0; e < 4; e++) {
                float p = __expf(s[mt][nt][e] - mx[mt][e >> 1]);
                s[mt][nt][e] = p;
                sum[mt][e >> 1] += p;
            }
        }
    float inv[2][2];
#pragma unroll
    for (int mt = 0; mt < 2; mt++)
#pragma unroll
        for (int hi = 0; hi < 2; hi++) {
            float v = sum[mt][hi];
            v += __shfl_xor_sync(0xffffffffu, v, 1);
            v += __shfl_xor_sync(0xffffffffu, v, 2);
            inv[mt][hi] = 1.f / v;
        }

    // ---- O = P V^T (m32 x n32 x k64); P fragments packed from s regs ----
    float o[2][4][4];
#pragma unroll
    for (int mt = 0; mt < 2; mt++)
#pragma unroll
        for (int nt = 0; nt < 4; nt++)
#pragma unroll
            for (int e = 0; e < 4; e++) o[mt][nt][e] = 0.f;

#pragma unroll
    for (int kt = 0; kt < 4; kt++) {
        uint32_t a[2][4];
#pragma unroll
        for (int mt = 0; mt < 2; mt++) {
            a[mt][0] = pack_h2(s[mt][2 * kt][0] * inv[mt][0], s[mt][2 * kt][1] * inv[mt][0]);
            a[mt][1] = pack_h2(s[mt][2 * kt][2] * inv[mt][1], s[mt][2 * kt][3] * inv[mt][1]);
            a[mt][2] = pack_h2(s[mt][2 * kt + 1][0] * inv[mt][0], s[mt][2 * kt + 1][1] * inv[mt][0]);
            a[mt][3] = pack_h2(s[mt][2 * kt + 1][2] * inv[mt][1], s[mt][2 * kt + 1][3] * inv[mt][1]);
        }
        const int j2a = 8 * kt + t;
        const int j2b = j2a + 4;
#pragma unroll
        for (int nt = 0; nt < 4; nt++) {
            int c = 8 * nt + g;
            uint32_t b0 = Vt[j2a * 40 + (c ^ (j2a >> 2))];
            uint32_t b1 = Vt[j2b * 40 + (c ^ (j2b >> 2))];
#pragma unroll
            for (int mt = 0; mt < 2; mt++)
                mma_f16(o[mt][nt][0], o[mt][nt][1], o[mt][nt][2], o[mt][nt][3],
                        a[mt][0], a[mt][1], a[mt][2], a[mt][3], b0, b1);
        }
    }

    // ---- epilogue: fp16 write to g_aow in window layout ----
#pragma unroll
    for (int mt = 0; mt < 2; mt++)
#pragma unroll
        for (int nt = 0; nt < 4; nt++)
#pragma unroll
            for (int e = 0; e < 4; e++) {
                int rp  = g + 8 * (e >> 1) + 16 * mt;
                int tok = w * 32 + rp;
                int cl  = 2 * t + (e & 1) + 8 * nt;
                g_aow[src + (size_t)cl * 64 + tok] = __float2half(o[mt][nt][e]);
            }
}

// ---------------------------------------------------------------------------
extern "C" void kernel_launch(void* const* d_in, const int* in_sizes, int n_in,
                              void* d_out, int out_size)
{
    const float* x  = (const float*)d_in[0];
    const float* Wq = (const float*)d_in[1];
    const float* Wk = (const float*)d_in[2];
    const float* Wv = (const float*)d_in[3];
    const float* Wo = (const float*)d_in[4];
    float* out = (float*)d_out;

    swz_kernel<<<128, 256>>>(Wq, Wk, Wv, Wo);
    qkv_kernel<<<dim3(6, NTILE), 256>>>(x);
    attn_tc_kernel<<<BB * NWIN * HEADS, 64>>>();
    wo_kernel<<<dim3(2, NTILE), 256>>>(out);
}